// round 9
// baseline (speedup 1.0000x reference)
#include <cuda_runtime.h>
#include <cstdint>

#define SEQ  4096
#define DIN  768
#define DOUT 768

// Scratch (allocation-free: __device__ globals).
__device__ float g_Q[SEQ * DOUT];
__device__ float g_K[SEQ * DOUT];
__device__ float g_V[SEQ * DOUT];
__device__ float g_Vt[DOUT * SEQ];         // V transposed [768][4096]
__device__ float g_E[(size_t)SEQ * SEQ];   // exp(scores)
__device__ float g_inv[SEQ];               // 1 / rowsum(E)
__device__ float g_P[3][SEQ * DOUT];       // AV split-K partials

// Split-K partition of K=4096 into 3 chunks (multiples of 16).
#define AV_K0 1376
#define AV_K1 1360

// ---------------------------------------------------------------------------
// helpers
// ---------------------------------------------------------------------------
__device__ __forceinline__ uint32_t f2tf32(float f) {
    uint32_t r;
    asm("cvt.rna.tf32.f32 %0, %1;" : "=r"(r) : "f"(f));
    return r;
}
__device__ __forceinline__ uint32_t bits2tf32(uint32_t b) {
    return f2tf32(__uint_as_float(b));
}

__device__ __forceinline__ void ldsm4(uint32_t r[4], uint32_t saddr) {
    asm volatile("ldmatrix.sync.aligned.m8n8.x4.shared.b16 {%0,%1,%2,%3}, [%4];"
                 : "=r"(r[0]), "=r"(r[1]), "=r"(r[2]), "=r"(r[3])
                 : "r"(saddr));
}

__device__ __forceinline__ void mma_tf32(float c[4],
                                         const uint32_t a[4],
                                         uint32_t b0, uint32_t b1) {
    asm volatile(
        "mma.sync.aligned.m16n8k8.row.col.f32.tf32.tf32.f32 "
        "{%0,%1,%2,%3}, {%4,%5,%6,%7}, {%8,%9}, {%0,%1,%2,%3};"
        : "+f"(c[0]), "+f"(c[1]), "+f"(c[2]), "+f"(c[3])
        : "r"(a[0]), "r"(a[1]), "r"(a[2]), "r"(a[3]), "r"(b0), "r"(b1));
}

__device__ __forceinline__ void cp_async16(uint32_t smem_dst, const void* gmem_src) {
    asm volatile("cp.async.cg.shared.global [%0], [%1], 16;"
                 :: "r"(smem_dst), "l"(gmem_src));
}
#define CP_COMMIT()  asm volatile("cp.async.commit_group;" ::: "memory")
#define CP_WAIT1()   asm volatile("cp.async.wait_group 1;" ::: "memory")

// smem layout: tile [rows][16 k-floats] as 16B chunks, XOR swizzled.
__device__ __forceinline__ int sw16(int row, int c) {
    return row * 4 + (c ^ ((row >> 1) & 3));
}

// ---------------------------------------------------------------------------
// Pipelined tf32 GEMM (both operands K-major / "TRANS_B" layout):
//   C[M,N] (+epilogue) from A[*, lda] rows bm.., B[*, ldb] rows bn..,
//   over K-range [kBegin, kBegin+kCount).
// Block 128x128, BK=16, 128 threads (4 warps 2x2, warp tile 64x64).
// cp.async 3-stage pipeline; fp32 in smem; tf32 cvt on fragments.
// MODE 1: C = exp(alpha*acc)   MODE 3: C = acc (split-K partial)
// ---------------------------------------------------------------------------
template <int MODE>
__global__ void __launch_bounds__(128, 2)
gemm_pipe(const float* __restrict__ A, const float* __restrict__ B,
          float* __restrict__ C, int lda, int ldb, int ldc,
          int kBegin, int kCount, float alpha)
{
    __shared__ float As[3][128 * 16];   // 24 KB
    __shared__ float Bs[3][128 * 16];   // 24 KB

    const int tid  = threadIdx.x;
    const int lane = tid & 31;
    const int wid  = tid >> 5;
    const int bm = blockIdx.y * 128;
    const int bn = blockIdx.x * 128;

    const int warp_m = wid & 1;
    const int warp_n = wid >> 1;
    const int m_base = warp_m * 64;
    const int n_base = warp_n * 64;

    const int a_row  = lane & 15;
    const int a_csel = (lane >> 4) & 1;
    const int b_row  = (lane & 7) + ((lane & 16) >> 1);
    const int b_csel = (lane >> 3) & 1;

    const uint32_t as_base0 = (uint32_t)__cvta_generic_to_shared(&As[0][0]);
    const uint32_t bs_base0 = (uint32_t)__cvta_generic_to_shared(&Bs[0][0]);
    const uint32_t buf_bytes = 128 * 16 * 4;

    int lr[4];
#pragma unroll
    for (int i = 0; i < 4; ++i) lr[i] = (tid + 128 * i) >> 2;
    const int lc = tid & 3;

    // precomputed smem dst offsets (bytes) for the 4 copies per operand
    uint32_t sdst[4];
#pragma unroll
    for (int i = 0; i < 4; ++i) sdst[i] = sw16(lr[i], lc) * 16;

    float acc[4][8][4];
#pragma unroll
    for (int mt = 0; mt < 4; ++mt)
#pragma unroll
        for (int nt = 0; nt < 8; ++nt)
#pragma unroll
            for (int i = 0; i < 4; ++i) acc[mt][nt][i] = 0.0f;

    auto issue_tile = [&](int st, int k0) {
        const uint32_t as_s = as_base0 + (uint32_t)st * buf_bytes;
        const uint32_t bs_s = bs_base0 + (uint32_t)st * buf_bytes;
#pragma unroll
        for (int i = 0; i < 4; ++i)
            cp_async16(as_s + sdst[i], &A[(size_t)(bm + lr[i]) * lda + k0 + lc * 4]);
#pragma unroll
        for (int i = 0; i < 4; ++i)
            cp_async16(bs_s + sdst[i], &B[(size_t)(bn + lr[i]) * ldb + k0 + lc * 4]);
    };

    auto compute_tile = [&](int st) {
        const uint32_t as_b = as_base0 + (uint32_t)st * buf_bytes;
        const uint32_t bs_b = bs_base0 + (uint32_t)st * buf_bytes;
#pragma unroll
        for (int kk = 0; kk < 2; ++kk) {
            uint32_t af[4][4];
#pragma unroll
            for (int mt = 0; mt < 4; ++mt) {
                int m = m_base + mt * 16 + a_row;
                int c = 2 * kk + a_csel;
                ldsm4(af[mt], as_b + sw16(m, c) * 16);
#pragma unroll
                for (int i = 0; i < 4; ++i) af[mt][i] = bits2tf32(af[mt][i]);
            }
            uint32_t bf[4][4];
#pragma unroll
            for (int np = 0; np < 4; ++np) {
                int n = n_base + np * 16 + b_row;
                int c = 2 * kk + b_csel;
                ldsm4(bf[np], bs_b + sw16(n, c) * 16);
#pragma unroll
                for (int i = 0; i < 4; ++i) bf[np][i] = bits2tf32(bf[np][i]);
            }
#pragma unroll
            for (int mt = 0; mt < 4; ++mt)
#pragma unroll
                for (int nt = 0; nt < 8; ++nt)
                    mma_tf32(acc[mt][nt], af[mt],
                             bf[nt >> 1][(nt & 1) * 2],
                             bf[nt >> 1][(nt & 1) * 2 + 1]);
        }
    };

    const int niter = kCount / 16;

    // prologue: stages 0 and 1 in flight
    issue_tile(0, kBegin);
    CP_COMMIT();
    if (niter > 1) issue_tile(1, kBegin + 16);
    CP_COMMIT();

    for (int it = 0; it < niter; ++it) {
        CP_WAIT1();            // group for stage `it` complete
        __syncthreads();       // all warps done with stage (it-1) reads
        const int nx = it + 2;
        if (nx < niter) issue_tile(nx - (nx / 3) * 3, kBegin + nx * 16);
        CP_COMMIT();
        compute_tile(it - (it / 3) * 3);
    }

    // --- writeback ---
    const int g = lane >> 2;
    const int tq = lane & 3;
#pragma unroll
    for (int mt = 0; mt < 4; ++mt) {
        const int r0 = bm + m_base + mt * 16 + g;
        const int r1 = r0 + 8;
#pragma unroll
        for (int nt = 0; nt < 8; ++nt) {
            const int col = bn + n_base + nt * 8 + tq * 2;
            float2 v0, v1;
            if (MODE == 1) {
                v0.x = __expf(alpha * acc[mt][nt][0]);
                v0.y = __expf(alpha * acc[mt][nt][1]);
                v1.x = __expf(alpha * acc[mt][nt][2]);
                v1.y = __expf(alpha * acc[mt][nt][3]);
            } else {
                v0.x = acc[mt][nt][0]; v0.y = acc[mt][nt][1];
                v1.x = acc[mt][nt][2]; v1.y = acc[mt][nt][3];
            }
            *reinterpret_cast<float2*>(&C[(size_t)r0 * ldc + col]) = v0;
            *reinterpret_cast<float2*>(&C[(size_t)r1 * ldc + col]) = v1;
        }
    }
}

// wrapper for AV split-K partials (per-z K range)
__global__ void __launch_bounds__(128, 2)
gemm_av_pipe(const float* __restrict__ E, const float* __restrict__ Vt,
             float* __restrict__ P)
{
    // forward into the shared template body via inline dispatch is not
    // possible for __global__; replicate the tiny bit of z-logic here by
    // calling the device path through a plain launch instead.
    // (This kernel is never launched; see kernel_launch which uses gemm_pipe.)
}

// ---------------------------------------------------------------------------
// V transpose: Vt[n][m] = V[m][n].  32x32 tiles via smem, coalesced.
// ---------------------------------------------------------------------------
__global__ void __launch_bounds__(256)
transpose_v(const float* __restrict__ V, float* __restrict__ Vt)
{
    __shared__ float ts[32][33];
    const int tx = threadIdx.x;        // 0..31
    const int ty = threadIdx.y;        // 0..7
    const int n0 = blockIdx.x * 32;    // col block in V (0..767)
    const int m0 = blockIdx.y * 32;    // row block in V (0..4095)

#pragma unroll
    for (int j = 0; j < 4; ++j) {
        int m = m0 + ty + j * 8;
        ts[ty + j * 8][tx] = V[(size_t)m * DOUT + n0 + tx];
    }
    __syncthreads();
#pragma unroll
    for (int j = 0; j < 4; ++j) {
        int n = n0 + ty + j * 8;
        Vt[(size_t)n * SEQ + m0 + tx] = ts[tx][ty + j * 8];
    }
}

// ---------------------------------------------------------------------------
// Reduce partials + apply row normalization.
// ---------------------------------------------------------------------------
__global__ void __launch_bounds__(256)
reduce_av(const float* __restrict__ P, const float* __restrict__ inv,
          float* __restrict__ out)
{
    const size_t stride = (size_t)SEQ * DOUT;
    const size_t i4 = (size_t)blockIdx.x * 256 + threadIdx.x;
    const size_t base = i4 * 4;
    const int row = (int)(base / DOUT);
    const float s = inv[row];

    float4 a = *reinterpret_cast<const float4*>(&P[base]);
    float4 b = *reinterpret_cast<const float4*>(&P[stride + base]);
    float4 c = *reinterpret_cast<const float4*>(&P[2 * stride + base]);
    float4 o;
    o.x = (a.x + b.x + c.x) * s;
    o.y = (a.y + b.y + c.y) * s;
    o.z = (a.z + b.z + c.z) * s;
    o.w = (a.w + b.w + c.w) * s;
    *reinterpret_cast<float4*>(&out[base]) = o;
}

// ---------------------------------------------------------------------------
// Batched QKV projection (validated): grid (18, 32); blockIdx.x/6 selects W.
// ---------------------------------------------------------------------------
__global__ void __launch_bounds__(256, 2)
proj_qkv(const float* __restrict__ A,
         const float* __restrict__ Wq, const float* __restrict__ Wk,
         const float* __restrict__ Wv,
         float* __restrict__ Qo, float* __restrict__ Ko, float* __restrict__ Vo)
{
    const int M = SEQ, N = DOUT, K = DIN;
    const int sel = blockIdx.x / 6;
    const float* B = (sel == 0) ? Wq : (sel == 1) ? Wk : Wv;
    float* C = (sel == 0) ? Qo : (sel == 1) ? Ko : Vo;

    __shared__ float As[2][128 * 16];
    __shared__ float Bs[2][128 * 16];

    const int tid  = threadIdx.x;
    const int lane = tid & 31;
    const int wid  = tid >> 5;
    const int bm = blockIdx.y * 128;
    const int bn = (blockIdx.x % 6) * 128;

    const int warp_m = wid & 1;
    const int warp_n = wid >> 1;
    const int m_base = warp_m * 64;
    const int n_base = warp_n * 32;

    const int a_row  = lane & 15;
    const int a_csel = (lane >> 4) & 1;
    const int b_row  = (lane & 7) + ((lane & 16) >> 1);
    const int b_csel = (lane >> 3) & 1;

    const uint32_t as_base0 = (uint32_t)__cvta_generic_to_shared(&As[0][0]);
    const uint32_t bs_base0 = (uint32_t)__cvta_generic_to_shared(&Bs[0][0]);
    const uint32_t buf_stride = 128 * 16 * 4;

    const int a_r0 = tid >> 2;
    const int a_c0 = tid & 3;
    const int a_r1 = (tid + 256) >> 2;
    const int bn_k0 = tid >> 7;
    const int bn_n0 = tid & 127;
    const int bn_k1 = (tid >> 7) + 2;

    float acc[4][4][4];
#pragma unroll
    for (int mt = 0; mt < 4; ++mt)
#pragma unroll
        for (int nt = 0; nt < 4; ++nt)
#pragma unroll
            for (int i = 0; i < 4; ++i) acc[mt][nt][i] = 0.0f;

    float4 pa0, pa1;
    float  pc0[4], pc1[4];

    auto ldg_tile = [&](int k0) {
        pa0 = *reinterpret_cast<const float4*>(&A[(size_t)(bm + a_r0) * K + k0 + a_c0 * 4]);
        pa1 = *reinterpret_cast<const float4*>(&A[(size_t)(bm + a_r1) * K + k0 + a_c0 * 4]);
#pragma unroll
        for (int j = 0; j < 4; ++j)
            pc0[j] = B[(size_t)(k0 + bn_k0 * 4 + j) * N + bn + bn_n0];
#pragma unroll
        for (int j = 0; j < 4; ++j)
            pc1[j] = B[(size_t)(k0 + bn_k1 * 4 + j) * N + bn + bn_n0];
    };

    auto sts_tile = [&](int b) {
        float4 t;
        t.x = __uint_as_float(f2tf32(pa0.x)); t.y = __uint_as_float(f2tf32(pa0.y));
        t.z = __uint_as_float(f2tf32(pa0.z)); t.w = __uint_as_float(f2tf32(pa0.w));
        *reinterpret_cast<float4*>(&As[b][sw16(a_r0, a_c0) * 4]) = t;
        t.x = __uint_as_float(f2tf32(pa1.x)); t.y = __uint_as_float(f2tf32(pa1.y));
        t.z = __uint_as_float(f2tf32(pa1.z)); t.w = __uint_as_float(f2tf32(pa1.w));
        *reinterpret_cast<float4*>(&As[b][sw16(a_r1, a_c0) * 4]) = t;
        t.x = __uint_as_float(f2tf32(pc0[0])); t.y = __uint_as_float(f2tf32(pc0[1]));
        t.z = __uint_as_float(f2tf32(pc0[2])); t.w = __uint_as_float(f2tf32(pc0[3]));
        *reinterpret_cast<float4*>(&Bs[b][sw16(bn_n0, bn_k0) * 4]) = t;
        t.x = __uint_as_float(f2tf32(pc1[0])); t.y = __uint_as_float(f2tf32(pc1[1]));
        t.z = __uint_as_float(f2tf32(pc1[2])); t.w = __uint_as_float(f2tf32(pc1[3]));
        *reinterpret_cast<float4*>(&Bs[b][sw16(bn_n0, bn_k1) * 4]) = t;
    };

    auto compute_tile = [&](int b) {
        const uint32_t as_b = as_base0 + (uint32_t)b * buf_stride;
        const uint32_t bs_b = bs_base0 + (uint32_t)b * buf_stride;
#pragma unroll
        for (int kk = 0; kk < 2; ++kk) {
            uint32_t af[4][4];
#pragma unroll
            for (int mt = 0; mt < 4; ++mt) {
                int m = m_base + mt * 16 + a_row;
                int c = 2 * kk + a_csel;
                ldsm4(af[mt], as_b + sw16(m, c) * 16);
            }
            uint32_t bf[2][4];
#pragma unroll
            for (int np = 0; np < 2; ++np) {
                int n = n_base + np * 16 + b_row;
                int c = 2 * kk + b_csel;
                ldsm4(bf[np], bs_b + sw16(n, c) * 16);
            }
#pragma unroll
            for (int mt = 0; mt < 4; ++mt)
#pragma unroll
                for (int nt = 0; nt < 4; ++nt)
                    mma_tf32(acc[mt][nt], af[mt],
                             bf[nt >> 1][(nt & 1) * 2],
                             bf[nt >> 1][(nt & 1) * 2 + 1]);
        }
    };

    ldg_tile(0);
    sts_tile(0);
    __syncthreads();

    const int niter = K / 16;
    int buf = 0;
    for (int it = 1; it < niter; ++it) {
        ldg_tile(it * 16);
        compute_tile(buf);
        sts_tile(buf ^ 1);
        __syncthreads();
        buf ^= 1;
    }
    compute_tile(buf);

    const int g = lane >> 2;
    const int tq = lane & 3;
#pragma unroll
    for (int mt = 0; mt < 4; ++mt) {
#pragma unroll
        for (int nt = 0; nt < 4; ++nt) {
            const int col = bn + n_base + nt * 8 + tq * 2;
            const int r0 = bm + m_base + mt * 16 + g;
            const int r1 = r0 + 8;
            float2 v0, v1;
            v0.x = acc[mt][nt][0]; v0.y = acc[mt][nt][1];
            v1.x = acc[mt][nt][2]; v1.y = acc[mt][nt][3];
            *reinterpret_cast<float2*>(&C[(size_t)r0 * N + col]) = v0;
            *reinterpret_cast<float2*>(&C[(size_t)r1 * N + col]) = v1;
        }
    }
}

// ---------------------------------------------------------------------------
// Row-sum reciprocal: inv[row] = 1 / sum(E[row, :]). Deterministic.
// ---------------------------------------------------------------------------
__global__ void __launch_bounds__(256)
rowinv_kernel(const float* __restrict__ E, float* __restrict__ inv)
{
    const int row = blockIdx.x;
    const int tid = threadIdx.x;
    const float* p = E + (size_t)row * SEQ;

    __shared__ float sm_red[8];

    float s = 0.0f;
#pragma unroll
    for (int it = 0; it < 4; ++it) {
        float4 t = *reinterpret_cast<const float4*>(&p[it * 1024 + tid * 4]);
        s += t.x + t.y + t.z + t.w;
    }
#pragma unroll
    for (int o = 16; o > 0; o >>= 1) s += __shfl_xor_sync(0xffffffffu, s, o);
    if ((tid & 31) == 0) sm_red[tid >> 5] = s;
    __syncthreads();
    if (tid == 0) {
        float ss = sm_red[0];
#pragma unroll
        for (int w = 1; w < 8; ++w) ss += sm_red[w];
        inv[row] = 1.0f / ss;
    }
}

// ---------------------------------------------------------------------------
// AV split-K via gemm_pipe: launched once per z with different K-range.
// ---------------------------------------------------------------------------
extern "C" void kernel_launch(void* const* d_in, const int* in_sizes, int n_in,
                              void* d_out, int out_size)
{
    const float* x  = (const float*)d_in[0];
    const float* Wq = (const float*)d_in[1];
    const float* Wk = (const float*)d_in[2];
    const float* Wv = (const float*)d_in[3];
    float* out = (float*)d_out;

    float* Q;   cudaGetSymbolAddress((void**)&Q,   g_Q);
    float* K_;  cudaGetSymbolAddress((void**)&K_,  g_K);
    float* V;   cudaGetSymbolAddress((void**)&V,   g_V);
    float* Vt;  cudaGetSymbolAddress((void**)&Vt,  g_Vt);
    float* E;   cudaGetSymbolAddress((void**)&E,   g_E);
    float* inv; cudaGetSymbolAddress((void**)&inv, g_inv);
    float* P;   cudaGetSymbolAddress((void**)&P,   g_P);

    const float inv_sqrt_d = 0.036084391824351615f;  // 1/sqrt(768)
    const size_t pstride = (size_t)SEQ * DOUT;

    dim3 grid_proj(18, SEQ / 128);            // batched Q,K,V
    dim3 grid_tr(DOUT / 32, SEQ / 32);        // V transpose
    dim3 blk_tr(32, 8);
    dim3 grid_ss(SEQ / 128, SEQ / 128);       // (32, 32)
    dim3 grid_av(DOUT / 128, SEQ / 128);      // (6, 32) per split

    // Q, K, V projections in one launch (576 CTAs)
    proj_qkv<<<grid_proj, 256>>>(x, Wq, Wk, Wv, Q, K_, V);

    // Vt = V^T  (for 16B-copy AV mainloop)
    transpose_v<<<grid_tr, blk_tr>>>(V, Vt);

    // E = exp(Q @ K^T / sqrt(d))   (3-stage cp.async pipeline)
    gemm_pipe<1><<<grid_ss, 128>>>(Q, K_, E, DIN, DIN, SEQ, 0, DIN, inv_sqrt_d);

    // inv[row] = 1 / rowsum(E)
    rowinv_kernel<<<SEQ, 256>>>(E, inv);

    // P[z] = E[:, Kz] @ Vt[:, Kz]^T   (split-K=3; three concurrent launches
    // would serialize on one stream anyway — issue as 3 launches back-to-back;
    // each fills 192 CTAs, together they pipeline across the tail)
    gemm_pipe<3><<<grid_av, 128>>>(E, Vt, P,               SEQ, SEQ, DOUT, 0,               AV_K0, 1.0f);
    gemm_pipe<3><<<grid_av, 128>>>(E, Vt, P + pstride,     SEQ, SEQ, DOUT, AV_K0,          AV_K1, 1.0f);
    gemm_pipe<3><<<grid_av, 128>>>(E, Vt, P + 2 * pstride, SEQ, SEQ, DOUT, AV_K0 + AV_K1,  AV_K1, 1.0f);

    // out = (P0 + P1 + P2) * inv[row]
    reduce_av<<<(SEQ * DOUT) / (256 * 4), 256>>>(P, inv, out);
}

// round 10
// speedup vs baseline: 1.1856x; 1.1856x over previous
#include <cuda_runtime.h>
#include <cstdint>

#define SEQ  4096
#define DIN  768
#define DOUT 768

// Scratch (allocation-free: __device__ globals).
__device__ float g_Q[SEQ * DOUT];
__device__ float g_K[SEQ * DOUT];
__device__ float g_V[SEQ * DOUT];
__device__ float g_Vt[DOUT * SEQ];         // V transposed [768][4096]
__device__ float g_E[(size_t)SEQ * SEQ];   // exp(scores)
__device__ float g_inv[SEQ];               // 1 / rowsum(E)
__device__ float g_P[3][SEQ * DOUT];       // AV split-K partials

// Split-K partition of K=4096 into 3 chunks (multiples of 16).
#define AV_K0 1376
#define AV_K1 1360

// ---------------------------------------------------------------------------
// helpers
// ---------------------------------------------------------------------------
__device__ __forceinline__ uint32_t f2tf32(float f) {
    uint32_t r;
    asm("cvt.rna.tf32.f32 %0, %1;" : "=r"(r) : "f"(f));
    return r;
}
__device__ __forceinline__ uint32_t bits2tf32(uint32_t b) {
    return f2tf32(__uint_as_float(b));
}

__device__ __forceinline__ void ldsm4(uint32_t r[4], uint32_t saddr) {
    asm volatile("ldmatrix.sync.aligned.m8n8.x4.shared.b16 {%0,%1,%2,%3}, [%4];"
                 : "=r"(r[0]), "=r"(r[1]), "=r"(r[2]), "=r"(r[3])
                 : "r"(saddr));
}

__device__ __forceinline__ void mma_tf32(float c[4],
                                         const uint32_t a[4],
                                         uint32_t b0, uint32_t b1) {
    asm volatile(
        "mma.sync.aligned.m16n8k8.row.col.f32.tf32.tf32.f32 "
        "{%0,%1,%2,%3}, {%4,%5,%6,%7}, {%8,%9}, {%0,%1,%2,%3};"
        : "+f"(c[0]), "+f"(c[1]), "+f"(c[2]), "+f"(c[3])
        : "r"(a[0]), "r"(a[1]), "r"(a[2]), "r"(a[3]), "r"(b0), "r"(b1));
}

__device__ __forceinline__ void cp_async16(uint32_t smem_dst, const void* gmem_src) {
    asm volatile("cp.async.cg.shared.global [%0], [%1], 16;"
                 :: "r"(smem_dst), "l"(gmem_src));
}
#define CP_COMMIT()  asm volatile("cp.async.commit_group;" ::: "memory")
#define CP_WAIT1()   asm volatile("cp.async.wait_group 1;" ::: "memory")

// smem layout: tile [rows][16 k-floats] as 16B chunks, XOR swizzled.
__device__ __forceinline__ int sw16(int row, int c) {
    return row * 4 + (c ^ ((row >> 1) & 3));
}

// ---------------------------------------------------------------------------
// Pipelined tf32 GEMM (both operands K-major):
// Block 128x128, BK=16, 128 threads (4 warps 2x2, warp tile 64x64).
// cp.async 3-stage pipeline; fp32 in smem; tf32 cvt on fragments.
// MODE 1: C = exp(alpha * A@B^T), K-range [0, kTot)            (QK^T + exp)
// MODE 3: split-K partial via blockIdx.z: P[z] = A@B^T over Kz (AV with Vt)
// ---------------------------------------------------------------------------
template <int MODE>
__global__ void __launch_bounds__(128, 2)
gemm_pipe(const float* __restrict__ A, const float* __restrict__ B,
          float* __restrict__ Cbase, int lda, int ldb, int ldc,
          int kTot, float alpha)
{
    __shared__ float As[3][128 * 16];   // 24 KB
    __shared__ float Bs[3][128 * 16];   // 24 KB

    const int tid  = threadIdx.x;
    const int lane = tid & 31;
    const int wid  = tid >> 5;
    const int bm = blockIdx.y * 128;
    const int bn = blockIdx.x * 128;

    int kBegin, kCount;
    float* C;
    if (MODE == 3) {
        const int z = blockIdx.z;
        kBegin = (z == 0) ? 0 : AV_K0 + (z - 1) * AV_K1;
        kCount = (z == 0) ? AV_K0 : AV_K1;
        C = Cbase + (size_t)z * SEQ * DOUT;
    } else {
        kBegin = 0;
        kCount = kTot;
        C = Cbase;
    }

    const int warp_m = wid & 1;
    const int warp_n = wid >> 1;
    const int m_base = warp_m * 64;
    const int n_base = warp_n * 64;

    const int a_row  = lane & 15;
    const int a_csel = (lane >> 4) & 1;
    const int b_row  = (lane & 7) + ((lane & 16) >> 1);
    const int b_csel = (lane >> 3) & 1;

    const uint32_t as_base0 = (uint32_t)__cvta_generic_to_shared(&As[0][0]);
    const uint32_t bs_base0 = (uint32_t)__cvta_generic_to_shared(&Bs[0][0]);
    const uint32_t buf_bytes = 128 * 16 * 4;

    int lr[4];
#pragma unroll
    for (int i = 0; i < 4; ++i) lr[i] = (tid + 128 * i) >> 2;
    const int lc = tid & 3;

    uint32_t sdst[4];
#pragma unroll
    for (int i = 0; i < 4; ++i) sdst[i] = sw16(lr[i], lc) * 16;

    float acc[4][8][4];
#pragma unroll
    for (int mt = 0; mt < 4; ++mt)
#pragma unroll
        for (int nt = 0; nt < 8; ++nt)
#pragma unroll
            for (int i = 0; i < 4; ++i) acc[mt][nt][i] = 0.0f;

    auto issue_tile = [&](int st, int k0) {
        const uint32_t as_s = as_base0 + (uint32_t)st * buf_bytes;
        const uint32_t bs_s = bs_base0 + (uint32_t)st * buf_bytes;
#pragma unroll
        for (int i = 0; i < 4; ++i)
            cp_async16(as_s + sdst[i], &A[(size_t)(bm + lr[i]) * lda + k0 + lc * 4]);
#pragma unroll
        for (int i = 0; i < 4; ++i)
            cp_async16(bs_s + sdst[i], &B[(size_t)(bn + lr[i]) * ldb + k0 + lc * 4]);
    };

    auto compute_tile = [&](int st) {
        const uint32_t as_b = as_base0 + (uint32_t)st * buf_bytes;
        const uint32_t bs_b = bs_base0 + (uint32_t)st * buf_bytes;
#pragma unroll
        for (int kk = 0; kk < 2; ++kk) {
            uint32_t af[4][4];
#pragma unroll
            for (int mt = 0; mt < 4; ++mt) {
                int m = m_base + mt * 16 + a_row;
                int c = 2 * kk + a_csel;
                ldsm4(af[mt], as_b + sw16(m, c) * 16);
#pragma unroll
                for (int i = 0; i < 4; ++i) af[mt][i] = bits2tf32(af[mt][i]);
            }
            uint32_t bf[4][4];
#pragma unroll
            for (int np = 0; np < 4; ++np) {
                int n = n_base + np * 16 + b_row;
                int c = 2 * kk + b_csel;
                ldsm4(bf[np], bs_b + sw16(n, c) * 16);
#pragma unroll
                for (int i = 0; i < 4; ++i) bf[np][i] = bits2tf32(bf[np][i]);
            }
#pragma unroll
            for (int mt = 0; mt < 4; ++mt)
#pragma unroll
                for (int nt = 0; nt < 8; ++nt)
                    mma_tf32(acc[mt][nt], af[mt],
                             bf[nt >> 1][(nt & 1) * 2],
                             bf[nt >> 1][(nt & 1) * 2 + 1]);
        }
    };

    const int niter = kCount / 16;

    // prologue: stages 0 and 1 in flight
    issue_tile(0, kBegin);
    CP_COMMIT();
    if (niter > 1) issue_tile(1, kBegin + 16);
    CP_COMMIT();

    for (int it = 0; it < niter; ++it) {
        CP_WAIT1();            // group for stage `it` complete
        __syncthreads();       // all warps done with stage (it-1) reads
        const int nx = it + 2;
        if (nx < niter) issue_tile(nx - (nx / 3) * 3, kBegin + nx * 16);
        CP_COMMIT();
        compute_tile(it - (it / 3) * 3);
    }

    // --- writeback ---
    const int g = lane >> 2;
    const int tq = lane & 3;
#pragma unroll
    for (int mt = 0; mt < 4; ++mt) {
        const int r0 = bm + m_base + mt * 16 + g;
        const int r1 = r0 + 8;
#pragma unroll
        for (int nt = 0; nt < 8; ++nt) {
            const int col = bn + n_base + nt * 8 + tq * 2;
            float2 v0, v1;
            if (MODE == 1) {
                v0.x = __expf(alpha * acc[mt][nt][0]);
                v0.y = __expf(alpha * acc[mt][nt][1]);
                v1.x = __expf(alpha * acc[mt][nt][2]);
                v1.y = __expf(alpha * acc[mt][nt][3]);
            } else {
                v0.x = acc[mt][nt][0]; v0.y = acc[mt][nt][1];
                v1.x = acc[mt][nt][2]; v1.y = acc[mt][nt][3];
            }
            *reinterpret_cast<float2*>(&C[(size_t)r0 * ldc + col]) = v0;
            *reinterpret_cast<float2*>(&C[(size_t)r1 * ldc + col]) = v1;
        }
    }
}

// ---------------------------------------------------------------------------
// V transpose: Vt[n][m] = V[m][n].  32x32 tiles via smem, coalesced.
// ---------------------------------------------------------------------------
__global__ void __launch_bounds__(256)
transpose_v(const float* __restrict__ V, float* __restrict__ Vt)
{
    __shared__ float ts[32][33];
    const int tx = threadIdx.x;        // 0..31
    const int ty = threadIdx.y;        // 0..7
    const int n0 = blockIdx.x * 32;    // col block in V (0..767)
    const int m0 = blockIdx.y * 32;    // row block in V (0..4095)

#pragma unroll
    for (int j = 0; j < 4; ++j) {
        int m = m0 + ty + j * 8;
        ts[ty + j * 8][tx] = V[(size_t)m * DOUT + n0 + tx];
    }
    __syncthreads();
#pragma unroll
    for (int j = 0; j < 4; ++j) {
        int n = n0 + ty + j * 8;
        Vt[(size_t)n * SEQ + m0 + tx] = ts[tx][ty + j * 8];
    }
}

// ---------------------------------------------------------------------------
// Reduce partials + apply row normalization.
// ---------------------------------------------------------------------------
__global__ void __launch_bounds__(256)
reduce_av(const float* __restrict__ P, const float* __restrict__ inv,
          float* __restrict__ out)
{
    const size_t stride = (size_t)SEQ * DOUT;
    const size_t i4 = (size_t)blockIdx.x * 256 + threadIdx.x;
    const size_t base = i4 * 4;
    const int row = (int)(base / DOUT);
    const float s = inv[row];

    float4 a = *reinterpret_cast<const float4*>(&P[base]);
    float4 b = *reinterpret_cast<const float4*>(&P[stride + base]);
    float4 c = *reinterpret_cast<const float4*>(&P[2 * stride + base]);
    float4 o;
    o.x = (a.x + b.x + c.x) * s;
    o.y = (a.y + b.y + c.y) * s;
    o.z = (a.z + b.z + c.z) * s;
    o.w = (a.w + b.w + c.w) * s;
    *reinterpret_cast<float4*>(&out[base]) = o;
}

// ---------------------------------------------------------------------------
// Batched QKV projection (validated): grid (18, 32); blockIdx.x/6 selects W.
// ---------------------------------------------------------------------------
__global__ void __launch_bounds__(256, 2)
proj_qkv(const float* __restrict__ A,
         const float* __restrict__ Wq, const float* __restrict__ Wk,
         const float* __restrict__ Wv,
         float* __restrict__ Qo, float* __restrict__ Ko, float* __restrict__ Vo)
{
    const int M = SEQ, N = DOUT, K = DIN;
    const int sel = blockIdx.x / 6;
    const float* B = (sel == 0) ? Wq : (sel == 1) ? Wk : Wv;
    float* C = (sel == 0) ? Qo : (sel == 1) ? Ko : Vo;

    __shared__ float As[2][128 * 16];
    __shared__ float Bs[2][128 * 16];

    const int tid  = threadIdx.x;
    const int lane = tid & 31;
    const int wid  = tid >> 5;
    const int bm = blockIdx.y * 128;
    const int bn = (blockIdx.x % 6) * 128;

    const int warp_m = wid & 1;
    const int warp_n = wid >> 1;
    const int m_base = warp_m * 64;
    const int n_base = warp_n * 32;

    const int a_row  = lane & 15;
    const int a_csel = (lane >> 4) & 1;
    const int b_row  = (lane & 7) + ((lane & 16) >> 1);
    const int b_csel = (lane >> 3) & 1;

    const uint32_t as_base0 = (uint32_t)__cvta_generic_to_shared(&As[0][0]);
    const uint32_t bs_base0 = (uint32_t)__cvta_generic_to_shared(&Bs[0][0]);
    const uint32_t buf_stride = 128 * 16 * 4;

    const int a_r0 = tid >> 2;
    const int a_c0 = tid & 3;
    const int a_r1 = (tid + 256) >> 2;
    const int bn_k0 = tid >> 7;
    const int bn_n0 = tid & 127;
    const int bn_k1 = (tid >> 7) + 2;

    float acc[4][4][4];
#pragma unroll
    for (int mt = 0; mt < 4; ++mt)
#pragma unroll
        for (int nt = 0; nt < 4; ++nt)
#pragma unroll
            for (int i = 0; i < 4; ++i) acc[mt][nt][i] = 0.0f;

    float4 pa0, pa1;
    float  pc0[4], pc1[4];

    auto ldg_tile = [&](int k0) {
        pa0 = *reinterpret_cast<const float4*>(&A[(size_t)(bm + a_r0) * K + k0 + a_c0 * 4]);
        pa1 = *reinterpret_cast<const float4*>(&A[(size_t)(bm + a_r1) * K + k0 + a_c0 * 4]);
#pragma unroll
        for (int j = 0; j < 4; ++j)
            pc0[j] = B[(size_t)(k0 + bn_k0 * 4 + j) * N + bn + bn_n0];
#pragma unroll
        for (int j = 0; j < 4; ++j)
            pc1[j] = B[(size_t)(k0 + bn_k1 * 4 + j) * N + bn + bn_n0];
    };

    auto sts_tile = [&](int b) {
        float4 t;
        t.x = __uint_as_float(f2tf32(pa0.x)); t.y = __uint_as_float(f2tf32(pa0.y));
        t.z = __uint_as_float(f2tf32(pa0.z)); t.w = __uint_as_float(f2tf32(pa0.w));
        *reinterpret_cast<float4*>(&As[b][sw16(a_r0, a_c0) * 4]) = t;
        t.x = __uint_as_float(f2tf32(pa1.x)); t.y = __uint_as_float(f2tf32(pa1.y));
        t.z = __uint_as_float(f2tf32(pa1.z)); t.w = __uint_as_float(f2tf32(pa1.w));
        *reinterpret_cast<float4*>(&As[b][sw16(a_r1, a_c0) * 4]) = t;
        t.x = __uint_as_float(f2tf32(pc0[0])); t.y = __uint_as_float(f2tf32(pc0[1]));
        t.z = __uint_as_float(f2tf32(pc0[2])); t.w = __uint_as_float(f2tf32(pc0[3]));
        *reinterpret_cast<float4*>(&Bs[b][sw16(bn_n0, bn_k0) * 4]) = t;
        t.x = __uint_as_float(f2tf32(pc1[0])); t.y = __uint_as_float(f2tf32(pc1[1]));
        t.z = __uint_as_float(f2tf32(pc1[2])); t.w = __uint_as_float(f2tf32(pc1[3]));
        *reinterpret_cast<float4*>(&Bs[b][sw16(bn_n0, bn_k1) * 4]) = t;
    };

    auto compute_tile = [&](int b) {
        const uint32_t as_b = as_base0 + (uint32_t)b * buf_stride;
        const uint32_t bs_b = bs_base0 + (uint32_t)b * buf_stride;
#pragma unroll
        for (int kk = 0; kk < 2; ++kk) {
            uint32_t af[4][4];
#pragma unroll
            for (int mt = 0; mt < 4; ++mt) {
                int m = m_base + mt * 16 + a_row;
                int c = 2 * kk + a_csel;
                ldsm4(af[mt], as_b + sw16(m, c) * 16);
            }
            uint32_t bf[2][4];
#pragma unroll
            for (int np = 0; np < 2; ++np) {
                int n = n_base + np * 16 + b_row;
                int c = 2 * kk + b_csel;
                ldsm4(bf[np], bs_b + sw16(n, c) * 16);
            }
#pragma unroll
            for (int mt = 0; mt < 4; ++mt)
#pragma unroll
                for (int nt = 0; nt < 4; ++nt)
                    mma_tf32(acc[mt][nt], af[mt],
                             bf[nt >> 1][(nt & 1) * 2],
                             bf[nt >> 1][(nt & 1) * 2 + 1]);
        }
    };

    ldg_tile(0);
    sts_tile(0);
    __syncthreads();

    const int niter = K / 16;
    int buf = 0;
    for (int it = 1; it < niter; ++it) {
        ldg_tile(it * 16);
        compute_tile(buf);
        sts_tile(buf ^ 1);
        __syncthreads();
        buf ^= 1;
    }
    compute_tile(buf);

    const int g = lane >> 2;
    const int tq = lane & 3;
#pragma unroll
    for (int mt = 0; mt < 4; ++mt) {
#pragma unroll
        for (int nt = 0; nt < 4; ++nt) {
            const int col = bn + n_base + nt * 8 + tq * 2;
            const int r0 = bm + m_base + mt * 16 + g;
            const int r1 = r0 + 8;
            float2 v0, v1;
            v0.x = acc[mt][nt][0]; v0.y = acc[mt][nt][1];
            v1.x = acc[mt][nt][2]; v1.y = acc[mt][nt][3];
            *reinterpret_cast<float2*>(&C[(size_t)r0 * N + col]) = v0;
            *reinterpret_cast<float2*>(&C[(size_t)r1 * N + col]) = v1;
        }
    }
}

// ---------------------------------------------------------------------------
// Row-sum reciprocal: inv[row] = 1 / sum(E[row, :]). Deterministic.
// ---------------------------------------------------------------------------
__global__ void __launch_bounds__(256)
rowinv_kernel(const float* __restrict__ E, float* __restrict__ inv)
{
    const int row = blockIdx.x;
    const int tid = threadIdx.x;
    const float* p = E + (size_t)row * SEQ;

    __shared__ float sm_red[8];

    float s = 0.0f;
#pragma unroll
    for (int it = 0; it < 4; ++it) {
        float4 t = *reinterpret_cast<const float4*>(&p[it * 1024 + tid * 4]);
        s += t.x + t.y + t.z + t.w;
    }
#pragma unroll
    for (int o = 16; o > 0; o >>= 1) s += __shfl_xor_sync(0xffffffffu, s, o);
    if ((tid & 31) == 0) sm_red[tid >> 5] = s;
    __syncthreads();
    if (tid == 0) {
        float ss = sm_red[0];
#pragma unroll
        for (int w = 1; w < 8; ++w) ss += sm_red[w];
        inv[row] = 1.0f / ss;
    }
}

// ---------------------------------------------------------------------------
extern "C" void kernel_launch(void* const* d_in, const int* in_sizes, int n_in,
                              void* d_out, int out_size)
{
    const float* x  = (const float*)d_in[0];
    const float* Wq = (const float*)d_in[1];
    const float* Wk = (const float*)d_in[2];
    const float* Wv = (const float*)d_in[3];
    float* out = (float*)d_out;

    float* Q;   cudaGetSymbolAddress((void**)&Q,   g_Q);
    float* K_;  cudaGetSymbolAddress((void**)&K_,  g_K);
    float* V;   cudaGetSymbolAddress((void**)&V,   g_V);
    float* Vt;  cudaGetSymbolAddress((void**)&Vt,  g_Vt);
    float* E;   cudaGetSymbolAddress((void**)&E,   g_E);
    float* inv; cudaGetSymbolAddress((void**)&inv, g_inv);
    float* P;   cudaGetSymbolAddress((void**)&P,   g_P);

    const float inv_sqrt_d = 0.036084391824351615f;  // 1/sqrt(768)

    dim3 grid_proj(18, SEQ / 128);            // batched Q,K,V
    dim3 grid_tr(DOUT / 32, SEQ / 32);        // V transpose
    dim3 blk_tr(32, 8);
    dim3 grid_ss(SEQ / 128, SEQ / 128);       // (32, 32)
    dim3 grid_av(DOUT / 128, SEQ / 128, 3);   // (6, 32, 3) split-K, ONE launch

    // Q, K, V projections in one launch (576 CTAs)
    proj_qkv<<<grid_proj, 256>>>(x, Wq, Wk, Wv, Q, K_, V);

    // Vt = V^T  (for 16B-copy AV mainloop)
    transpose_v<<<grid_tr, blk_tr>>>(V, Vt);

    // E = exp(Q @ K^T / sqrt(d))   (3-stage cp.async pipeline)
    gemm_pipe<1><<<grid_ss, 128>>>(Q, K_, E, DIN, DIN, SEQ, DIN, inv_sqrt_d);

    // inv[row] = 1 / rowsum(E)
    rowinv_kernel<<<SEQ, 256>>>(E, inv);

    // P[z] = E[:, Kz] @ Vt[:, Kz]^T   (split-K=3 in ONE 576-CTA launch)
    gemm_pipe<3><<<grid_av, 128>>>(E, Vt, P, SEQ, SEQ, DOUT, SEQ, 1.0f);

    // out = (P0 + P1 + P2) * inv[row]
    reduce_av<<<(SEQ * DOUT) / (256 * 4), 256>>>(P, inv, out);
}

// round 11
// speedup vs baseline: 1.3406x; 1.1308x over previous
#include <cuda_runtime.h>
#include <cstdint>

#define SEQ  4096
#define DIN  768
#define DOUT 768

// Scratch (allocation-free: __device__ globals).
__device__ float g_Q[SEQ * DOUT];
__device__ float g_K[SEQ * DOUT];
__device__ float g_V[SEQ * DOUT];
__device__ float g_Vt[DOUT * SEQ];         // V transposed [768][4096]
__device__ float g_E[(size_t)SEQ * SEQ];   // exp(scores), tf32-rounded
__device__ float g_inv[SEQ];               // 1 / rowsum(E)
__device__ float g_P[3][SEQ * DOUT];       // AV split-K partials

// Split-K partition of K=4096 into 3 chunks (multiples of 16).
#define AV_K0 1376
#define AV_K1 1360

// ---------------------------------------------------------------------------
// helpers
// ---------------------------------------------------------------------------
__device__ __forceinline__ uint32_t f2tf32(float f) {
    uint32_t r;
    asm("cvt.rna.tf32.f32 %0, %1;" : "=r"(r) : "f"(f));
    return r;
}
__device__ __forceinline__ float rnd_tf32(float f) {
    return __uint_as_float(f2tf32(f));
}

__device__ __forceinline__ void ldsm4(uint32_t r[4], uint32_t saddr) {
    asm volatile("ldmatrix.sync.aligned.m8n8.x4.shared.b16 {%0,%1,%2,%3}, [%4];"
                 : "=r"(r[0]), "=r"(r[1]), "=r"(r[2]), "=r"(r[3])
                 : "r"(saddr));
}

__device__ __forceinline__ void mma_tf32(float c[4],
                                         const uint32_t a[4],
                                         uint32_t b0, uint32_t b1) {
    asm volatile(
        "mma.sync.aligned.m16n8k8.row.col.f32.tf32.tf32.f32 "
        "{%0,%1,%2,%3}, {%4,%5,%6,%7}, {%8,%9}, {%0,%1,%2,%3};"
        : "+f"(c[0]), "+f"(c[1]), "+f"(c[2]), "+f"(c[3])
        : "r"(a[0]), "r"(a[1]), "r"(a[2]), "r"(a[3]), "r"(b0), "r"(b1));
}

__device__ __forceinline__ void cp_async16(uint32_t smem_dst, const void* gmem_src) {
    asm volatile("cp.async.cg.shared.global [%0], [%1], 16;"
                 :: "r"(smem_dst), "l"(gmem_src));
}
#define CP_COMMIT()  asm volatile("cp.async.commit_group;" ::: "memory")
#define CP_WAIT1()   asm volatile("cp.async.wait_group 1;" ::: "memory")

// smem layout: tile [rows][16 k-floats] as 16B chunks, XOR swizzled.
__device__ __forceinline__ int sw16(int row, int c) {
    return row * 4 + (c ^ ((row >> 1) & 3));
}

// ---------------------------------------------------------------------------
// Pipelined tf32 GEMM (both operands K-major, inputs PRE-ROUNDED to tf32):
// Block 128x128, BK=16, 128 threads (4 warps 2x2, warp tile 64x64).
// cp.async 3-stage pipeline; NO cvt in mainloop (inputs already tf32).
// MODE 1: C = tf32(exp(alpha * A@B^T)), K-range [0, kTot)      (QK^T + exp)
// MODE 3: split-K partial via blockIdx.z: P[z] = A@B^T over Kz (AV with Vt)
// ---------------------------------------------------------------------------
template <int MODE>
__global__ void __launch_bounds__(128, 2)
gemm_pipe(const float* __restrict__ A, const float* __restrict__ B,
          float* __restrict__ Cbase, int lda, int ldb, int ldc,
          int kTot, float alpha)
{
    __shared__ float As[3][128 * 16];   // 24 KB
    __shared__ float Bs[3][128 * 16];   // 24 KB

    const int tid  = threadIdx.x;
    const int lane = tid & 31;
    const int wid  = tid >> 5;
    const int bm = blockIdx.y * 128;
    const int bn = blockIdx.x * 128;

    int kBegin, kCount;
    float* C;
    if (MODE == 3) {
        const int z = blockIdx.z;
        kBegin = (z == 0) ? 0 : AV_K0 + (z - 1) * AV_K1;
        kCount = (z == 0) ? AV_K0 : AV_K1;
        C = Cbase + (size_t)z * SEQ * DOUT;
    } else {
        kBegin = 0;
        kCount = kTot;
        C = Cbase;
    }

    const int warp_m = wid & 1;
    const int warp_n = wid >> 1;
    const int m_base = warp_m * 64;
    const int n_base = warp_n * 64;

    const int a_row  = lane & 15;
    const int a_csel = (lane >> 4) & 1;
    const int b_row  = (lane & 7) + ((lane & 16) >> 1);
    const int b_csel = (lane >> 3) & 1;

    const uint32_t as_base0 = (uint32_t)__cvta_generic_to_shared(&As[0][0]);
    const uint32_t bs_base0 = (uint32_t)__cvta_generic_to_shared(&Bs[0][0]);
    const uint32_t buf_bytes = 128 * 16 * 4;

    int lr[4];
#pragma unroll
    for (int i = 0; i < 4; ++i) lr[i] = (tid + 128 * i) >> 2;
    const int lc = tid & 3;

    uint32_t sdst[4];
#pragma unroll
    for (int i = 0; i < 4; ++i) sdst[i] = sw16(lr[i], lc) * 16;

    float acc[4][8][4];
#pragma unroll
    for (int mt = 0; mt < 4; ++mt)
#pragma unroll
        for (int nt = 0; nt < 8; ++nt)
#pragma unroll
            for (int i = 0; i < 4; ++i) acc[mt][nt][i] = 0.0f;

    auto issue_tile = [&](int st, int k0) {
        const uint32_t as_s = as_base0 + (uint32_t)st * buf_bytes;
        const uint32_t bs_s = bs_base0 + (uint32_t)st * buf_bytes;
#pragma unroll
        for (int i = 0; i < 4; ++i)
            cp_async16(as_s + sdst[i], &A[(size_t)(bm + lr[i]) * lda + k0 + lc * 4]);
#pragma unroll
        for (int i = 0; i < 4; ++i)
            cp_async16(bs_s + sdst[i], &B[(size_t)(bn + lr[i]) * ldb + k0 + lc * 4]);
    };

    auto compute_tile = [&](int st) {
        const uint32_t as_b = as_base0 + (uint32_t)st * buf_bytes;
        const uint32_t bs_b = bs_base0 + (uint32_t)st * buf_bytes;
#pragma unroll
        for (int kk = 0; kk < 2; ++kk) {
            uint32_t af[4][4];
#pragma unroll
            for (int mt = 0; mt < 4; ++mt) {
                int m = m_base + mt * 16 + a_row;
                int c = 2 * kk + a_csel;
                ldsm4(af[mt], as_b + sw16(m, c) * 16);
            }
            uint32_t bf[4][4];
#pragma unroll
            for (int np = 0; np < 4; ++np) {
                int n = n_base + np * 16 + b_row;
                int c = 2 * kk + b_csel;
                ldsm4(bf[np], bs_b + sw16(n, c) * 16);
            }
#pragma unroll
            for (int mt = 0; mt < 4; ++mt)
#pragma unroll
                for (int nt = 0; nt < 8; ++nt)
                    mma_tf32(acc[mt][nt], af[mt],
                             bf[nt >> 1][(nt & 1) * 2],
                             bf[nt >> 1][(nt & 1) * 2 + 1]);
        }
    };

    const int niter = kCount / 16;

    // prologue: stages 0 and 1 in flight
    issue_tile(0, kBegin);
    CP_COMMIT();
    if (niter > 1) issue_tile(1, kBegin + 16);
    CP_COMMIT();

    for (int it = 0; it < niter; ++it) {
        CP_WAIT1();            // group for stage `it` complete
        __syncthreads();       // all warps done with stage (it-1) reads
        const int nx = it + 2;
        if (nx < niter) issue_tile(nx - (nx / 3) * 3, kBegin + nx * 16);
        CP_COMMIT();
        compute_tile(it - (it / 3) * 3);
    }

    // --- writeback ---
    const int g = lane >> 2;
    const int tq = lane & 3;
#pragma unroll
    for (int mt = 0; mt < 4; ++mt) {
        const int r0 = bm + m_base + mt * 16 + g;
        const int r1 = r0 + 8;
#pragma unroll
        for (int nt = 0; nt < 8; ++nt) {
            const int col = bn + n_base + nt * 8 + tq * 2;
            float2 v0, v1;
            if (MODE == 1) {
                // E is consumed by the AV GEMM as an mma operand: pre-round.
                v0.x = rnd_tf32(__expf(alpha * acc[mt][nt][0]));
                v0.y = rnd_tf32(__expf(alpha * acc[mt][nt][1]));
                v1.x = rnd_tf32(__expf(alpha * acc[mt][nt][2]));
                v1.y = rnd_tf32(__expf(alpha * acc[mt][nt][3]));
            } else {
                v0.x = acc[mt][nt][0]; v0.y = acc[mt][nt][1];
                v1.x = acc[mt][nt][2]; v1.y = acc[mt][nt][3];
            }
            *reinterpret_cast<float2*>(&C[(size_t)r0 * ldc + col]) = v0;
            *reinterpret_cast<float2*>(&C[(size_t)r1 * ldc + col]) = v1;
        }
    }
}

// ---------------------------------------------------------------------------
// V transpose: Vt[n][m] = V[m][n].  32x32 tiles via smem, coalesced.
// (V is already tf32-rounded by proj_qkv.)
// ---------------------------------------------------------------------------
__global__ void __launch_bounds__(256)
transpose_v(const float* __restrict__ V, float* __restrict__ Vt)
{
    __shared__ float ts[32][33];
    const int tx = threadIdx.x;        // 0..31
    const int ty = threadIdx.y;        // 0..7
    const int n0 = blockIdx.x * 32;    // col block in V (0..767)
    const int m0 = blockIdx.y * 32;    // row block in V (0..4095)

#pragma unroll
    for (int j = 0; j < 4; ++j) {
        int m = m0 + ty + j * 8;
        ts[ty + j * 8][tx] = V[(size_t)m * DOUT + n0 + tx];
    }
    __syncthreads();
#pragma unroll
    for (int j = 0; j < 4; ++j) {
        int n = n0 + ty + j * 8;
        Vt[(size_t)n * SEQ + m0 + tx] = ts[tx][ty + j * 8];
    }
}

// ---------------------------------------------------------------------------
// Reduce partials + apply row normalization.
// ---------------------------------------------------------------------------
__global__ void __launch_bounds__(256)
reduce_av(const float* __restrict__ P, const float* __restrict__ inv,
          float* __restrict__ out)
{
    const size_t stride = (size_t)SEQ * DOUT;
    const size_t i4 = (size_t)blockIdx.x * 256 + threadIdx.x;
    const size_t base = i4 * 4;
    const int row = (int)(base / DOUT);
    const float s = inv[row];

    float4 a = *reinterpret_cast<const float4*>(&P[base]);
    float4 b = *reinterpret_cast<const float4*>(&P[stride + base]);
    float4 c = *reinterpret_cast<const float4*>(&P[2 * stride + base]);
    float4 o;
    o.x = (a.x + b.x + c.x) * s;
    o.y = (a.y + b.y + c.y) * s;
    o.z = (a.z + b.z + c.z) * s;
    o.w = (a.w + b.w + c.w) * s;
    *reinterpret_cast<float4*>(&out[base]) = o;
}

// ---------------------------------------------------------------------------
// Batched QKV projection (validated): grid (18, 32); blockIdx.x/6 selects W.
// Outputs are tf32-rounded so downstream GEMMs need no mainloop cvt.
// ---------------------------------------------------------------------------
__global__ void __launch_bounds__(256, 2)
proj_qkv(const float* __restrict__ A,
         const float* __restrict__ Wq, const float* __restrict__ Wk,
         const float* __restrict__ Wv,
         float* __restrict__ Qo, float* __restrict__ Ko, float* __restrict__ Vo)
{
    const int M = SEQ, N = DOUT, K = DIN;
    const int sel = blockIdx.x / 6;
    const float* B = (sel == 0) ? Wq : (sel == 1) ? Wk : Wv;
    float* C = (sel == 0) ? Qo : (sel == 1) ? Ko : Vo;

    __shared__ float As[2][128 * 16];
    __shared__ float Bs[2][128 * 16];

    const int tid  = threadIdx.x;
    const int lane = tid & 31;
    const int wid  = tid >> 5;
    const int bm = blockIdx.y * 128;
    const int bn = (blockIdx.x % 6) * 128;

    const int warp_m = wid & 1;
    const int warp_n = wid >> 1;
    const int m_base = warp_m * 64;
    const int n_base = warp_n * 32;

    const int a_row  = lane & 15;
    const int a_csel = (lane >> 4) & 1;
    const int b_row  = (lane & 7) + ((lane & 16) >> 1);
    const int b_csel = (lane >> 3) & 1;

    const uint32_t as_base0 = (uint32_t)__cvta_generic_to_shared(&As[0][0]);
    const uint32_t bs_base0 = (uint32_t)__cvta_generic_to_shared(&Bs[0][0]);
    const uint32_t buf_stride = 128 * 16 * 4;

    const int a_r0 = tid >> 2;
    const int a_c0 = tid & 3;
    const int a_r1 = (tid + 256) >> 2;
    const int bn_k0 = tid >> 7;
    const int bn_n0 = tid & 127;
    const int bn_k1 = (tid >> 7) + 2;

    float acc[4][4][4];
#pragma unroll
    for (int mt = 0; mt < 4; ++mt)
#pragma unroll
        for (int nt = 0; nt < 4; ++nt)
#pragma unroll
            for (int i = 0; i < 4; ++i) acc[mt][nt][i] = 0.0f;

    float4 pa0, pa1;
    float  pc0[4], pc1[4];

    auto ldg_tile = [&](int k0) {
        pa0 = *reinterpret_cast<const float4*>(&A[(size_t)(bm + a_r0) * K + k0 + a_c0 * 4]);
        pa1 = *reinterpret_cast<const float4*>(&A[(size_t)(bm + a_r1) * K + k0 + a_c0 * 4]);
#pragma unroll
        for (int j = 0; j < 4; ++j)
            pc0[j] = B[(size_t)(k0 + bn_k0 * 4 + j) * N + bn + bn_n0];
#pragma unroll
        for (int j = 0; j < 4; ++j)
            pc1[j] = B[(size_t)(k0 + bn_k1 * 4 + j) * N + bn + bn_n0];
    };

    auto sts_tile = [&](int b) {
        float4 t;
        t.x = rnd_tf32(pa0.x); t.y = rnd_tf32(pa0.y);
        t.z = rnd_tf32(pa0.z); t.w = rnd_tf32(pa0.w);
        *reinterpret_cast<float4*>(&As[b][sw16(a_r0, a_c0) * 4]) = t;
        t.x = rnd_tf32(pa1.x); t.y = rnd_tf32(pa1.y);
        t.z = rnd_tf32(pa1.z); t.w = rnd_tf32(pa1.w);
        *reinterpret_cast<float4*>(&As[b][sw16(a_r1, a_c0) * 4]) = t;
        t.x = rnd_tf32(pc0[0]); t.y = rnd_tf32(pc0[1]);
        t.z = rnd_tf32(pc0[2]); t.w = rnd_tf32(pc0[3]);
        *reinterpret_cast<float4*>(&Bs[b][sw16(bn_n0, bn_k0) * 4]) = t;
        t.x = rnd_tf32(pc1[0]); t.y = rnd_tf32(pc1[1]);
        t.z = rnd_tf32(pc1[2]); t.w = rnd_tf32(pc1[3]);
        *reinterpret_cast<float4*>(&Bs[b][sw16(bn_n0, bn_k1) * 4]) = t;
    };

    auto compute_tile = [&](int b) {
        const uint32_t as_b = as_base0 + (uint32_t)b * buf_stride;
        const uint32_t bs_b = bs_base0 + (uint32_t)b * buf_stride;
#pragma unroll
        for (int kk = 0; kk < 2; ++kk) {
            uint32_t af[4][4];
#pragma unroll
            for (int mt = 0; mt < 4; ++mt) {
                int m = m_base + mt * 16 + a_row;
                int c = 2 * kk + a_csel;
                ldsm4(af[mt], as_b + sw16(m, c) * 16);
            }
            uint32_t bf[2][4];
#pragma unroll
            for (int np = 0; np < 2; ++np) {
                int n = n_base + np * 16 + b_row;
                int c = 2 * kk + b_csel;
                ldsm4(bf[np], bs_b + sw16(n, c) * 16);
            }
#pragma unroll
            for (int mt = 0; mt < 4; ++mt)
#pragma unroll
                for (int nt = 0; nt < 4; ++nt)
                    mma_tf32(acc[mt][nt], af[mt],
                             bf[nt >> 1][(nt & 1) * 2],
                             bf[nt >> 1][(nt & 1) * 2 + 1]);
        }
    };

    ldg_tile(0);
    sts_tile(0);
    __syncthreads();

    const int niter = K / 16;
    int buf = 0;
    for (int it = 1; it < niter; ++it) {
        ldg_tile(it * 16);
        compute_tile(buf);
        sts_tile(buf ^ 1);
        __syncthreads();
        buf ^= 1;
    }
    compute_tile(buf);

    const int g = lane >> 2;
    const int tq = lane & 3;
#pragma unroll
    for (int mt = 0; mt < 4; ++mt) {
#pragma unroll
        for (int nt = 0; nt < 4; ++nt) {
            const int col = bn + n_base + nt * 8 + tq * 2;
            const int r0 = bm + m_base + mt * 16 + g;
            const int r1 = r0 + 8;
            float2 v0, v1;
            // Pre-round outputs to tf32: downstream GEMMs skip mainloop cvt.
            v0.x = rnd_tf32(acc[mt][nt][0]); v0.y = rnd_tf32(acc[mt][nt][1]);
            v1.x = rnd_tf32(acc[mt][nt][2]); v1.y = rnd_tf32(acc[mt][nt][3]);
            *reinterpret_cast<float2*>(&C[(size_t)r0 * N + col]) = v0;
            *reinterpret_cast<float2*>(&C[(size_t)r1 * N + col]) = v1;
        }
    }
}

// ---------------------------------------------------------------------------
// Row-sum reciprocal: inv[row] = 1 / sum(E[row, :]). Deterministic.
// ---------------------------------------------------------------------------
__global__ void __launch_bounds__(256)
rowinv_kernel(const float* __restrict__ E, float* __restrict__ inv)
{
    const int row = blockIdx.x;
    const int tid = threadIdx.x;
    const float* p = E + (size_t)row * SEQ;

    __shared__ float sm_red[8];

    float s = 0.0f;
#pragma unroll
    for (int it = 0; it < 4; ++it) {
        float4 t = *reinterpret_cast<const float4*>(&p[it * 1024 + tid * 4]);
        s += t.x + t.y + t.z + t.w;
    }
#pragma unroll
    for (int o = 16; o > 0; o >>= 1) s += __shfl_xor_sync(0xffffffffu, s, o);
    if ((tid & 31) == 0) sm_red[tid >> 5] = s;
    __syncthreads();
    if (tid == 0) {
        float ss = sm_red[0];
#pragma unroll
        for (int w = 1; w < 8; ++w) ss += sm_red[w];
        inv[row] = 1.0f / ss;
    }
}

// ---------------------------------------------------------------------------
extern "C" void kernel_launch(void* const* d_in, const int* in_sizes, int n_in,
                              void* d_out, int out_size)
{
    const float* x  = (const float*)d_in[0];
    const float* Wq = (const float*)d_in[1];
    const float* Wk = (const float*)d_in[2];
    const float* Wv = (const float*)d_in[3];
    float* out = (float*)d_out;

    float* Q;   cudaGetSymbolAddress((void**)&Q,   g_Q);
    float* K_;  cudaGetSymbolAddress((void**)&K_,  g_K);
    float* V;   cudaGetSymbolAddress((void**)&V,   g_V);
    float* Vt;  cudaGetSymbolAddress((void**)&Vt,  g_Vt);
    float* E;   cudaGetSymbolAddress((void**)&E,   g_E);
    float* inv; cudaGetSymbolAddress((void**)&inv, g_inv);
    float* P;   cudaGetSymbolAddress((void**)&P,   g_P);

    const float inv_sqrt_d = 0.036084391824351615f;  // 1/sqrt(768)

    dim3 grid_proj(18, SEQ / 128);            // batched Q,K,V
    dim3 grid_tr(DOUT / 32, SEQ / 32);        // V transpose
    dim3 blk_tr(32, 8);
    dim3 grid_ss(SEQ / 128, SEQ / 128);       // (32, 32)
    dim3 grid_av(DOUT / 128, SEQ / 128, 3);   // (6, 32, 3) split-K, ONE launch

    // Q, K, V projections in one launch (576 CTAs); outputs tf32-rounded
    proj_qkv<<<grid_proj, 256>>>(x, Wq, Wk, Wv, Q, K_, V);

    // Vt = V^T
    transpose_v<<<grid_tr, blk_tr>>>(V, Vt);

    // E = tf32(exp(Q @ K^T / sqrt(d)))   (cvt-free mainloop)
    gemm_pipe<1><<<grid_ss, 128>>>(Q, K_, E, DIN, DIN, SEQ, DIN, inv_sqrt_d);

    // inv[row] = 1 / rowsum(E)
    rowinv_kernel<<<SEQ, 256>>>(E, inv);

    // P[z] = E[:, Kz] @ Vt[:, Kz]^T   (split-K=3 in ONE 576-CTA launch)
    gemm_pipe<3><<<grid_av, 128>>>(E, Vt, P, SEQ, SEQ, DOUT, SEQ, 1.0f);

    // out = (P0 + P1 + P2) * inv[row]
    reduce_av<<<(SEQ * DOUT) / (256 * 4), 256>>>(P, inv, out);
}

// round 14
// speedup vs baseline: 1.3676x; 1.0201x over previous
#include <cuda_runtime.h>
#include <cstdint>

#define SEQ  4096
#define DIN  768
#define DOUT 768

// Scratch (allocation-free: __device__ globals).
__device__ float g_Wt[3][DIN * DOUT];      // Wq/Wk/Wv transposed [N][K], tf32-rounded
__device__ float g_Q[SEQ * DOUT];
__device__ float g_K[SEQ * DOUT];
__device__ float g_Vt[DOUT * SEQ];         // V transposed [768][4096], tf32-rounded
__device__ float g_E[(size_t)SEQ * SEQ];   // exp(scores), tf32-rounded
__device__ float g_inv[SEQ];               // 1 / rowsum(E)
__device__ float g_P[3][SEQ * DOUT];       // AV split-K partials

// Split-K partition of K=4096 into 3 chunks (multiples of 16).
#define AV_K0 1376
#define AV_K1 1360

// ---------------------------------------------------------------------------
// helpers
// ---------------------------------------------------------------------------
__device__ __forceinline__ uint32_t f2tf32(float f) {
    uint32_t r;
    asm("cvt.rna.tf32.f32 %0, %1;" : "=r"(r) : "f"(f));
    return r;
}
__device__ __forceinline__ float rnd_tf32(float f) {
    return __uint_as_float(f2tf32(f));
}
__device__ __forceinline__ uint32_t bits2tf32(uint32_t b) {
    return f2tf32(__uint_as_float(b));
}

__device__ __forceinline__ void ldsm4(uint32_t r[4], uint32_t saddr) {
    asm volatile("ldmatrix.sync.aligned.m8n8.x4.shared.b16 {%0,%1,%2,%3}, [%4];"
                 : "=r"(r[0]), "=r"(r[1]), "=r"(r[2]), "=r"(r[3])
                 : "r"(saddr));
}

__device__ __forceinline__ void mma_tf32(float c[4],
                                         const uint32_t a[4],
                                         uint32_t b0, uint32_t b1) {
    asm volatile(
        "mma.sync.aligned.m16n8k8.row.col.f32.tf32.tf32.f32 "
        "{%0,%1,%2,%3}, {%4,%5,%6,%7}, {%8,%9}, {%0,%1,%2,%3};"
        : "+f"(c[0]), "+f"(c[1]), "+f"(c[2]), "+f"(c[3])
        : "r"(a[0]), "r"(a[1]), "r"(a[2]), "r"(a[3]), "r"(b0), "r"(b1));
}

__device__ __forceinline__ void cp_async16(uint32_t smem_dst, const void* gmem_src) {
    asm volatile("cp.async.cg.shared.global [%0], [%1], 16;"
                 :: "r"(smem_dst), "l"(gmem_src));
}
#define CP_COMMIT()  asm volatile("cp.async.commit_group;" ::: "memory")
#define CP_WAIT1()   asm volatile("cp.async.wait_group 1;" ::: "memory")

// smem layout: tile [rows][16 k-floats] as 16B chunks, XOR swizzled.
__device__ __forceinline__ int sw16(int row, int c) {
    return row * 4 + (c ^ ((row >> 1) & 3));
}

// ---------------------------------------------------------------------------
// Pipelined tf32 GEMM (both operands K-major, inputs PRE-ROUNDED to tf32):
// Block 128x128, BK=16, 128 threads (4 warps 2x2, warp tile 64x64).
// cp.async 3-stage pipeline; NO cvt in mainloop (inputs already tf32).
// MODE 1: C = tf32(exp(alpha * A@B^T)), K-range [0, kTot)      (QK^T + exp)
// MODE 3: split-K partial via blockIdx.z: P[z] = A@B^T over Kz (AV with Vt)
// ---------------------------------------------------------------------------
template <int MODE>
__global__ void __launch_bounds__(128, 2)
gemm_pipe(const float* __restrict__ A, const float* __restrict__ B,
          float* __restrict__ Cbase, int lda, int ldb, int ldc,
          int kTot, float alpha)
{
    __shared__ float As[3][128 * 16];   // 24 KB
    __shared__ float Bs[3][128 * 16];   // 24 KB

    const int tid  = threadIdx.x;
    const int lane = tid & 31;
    const int wid  = tid >> 5;
    const int bm = blockIdx.y * 128;
    const int bn = blockIdx.x * 128;

    int kBegin, kCount;
    float* C;
    if (MODE == 3) {
        const int z = blockIdx.z;
        kBegin = (z == 0) ? 0 : AV_K0 + (z - 1) * AV_K1;
        kCount = (z == 0) ? AV_K0 : AV_K1;
        C = Cbase + (size_t)z * SEQ * DOUT;
    } else {
        kBegin = 0;
        kCount = kTot;
        C = Cbase;
    }

    const int warp_m = wid & 1;
    const int warp_n = wid >> 1;
    const int m_base = warp_m * 64;
    const int n_base = warp_n * 64;

    const int a_row  = lane & 15;
    const int a_csel = (lane >> 4) & 1;
    const int b_row  = (lane & 7) + ((lane & 16) >> 1);
    const int b_csel = (lane >> 3) & 1;

    const uint32_t as_base0 = (uint32_t)__cvta_generic_to_shared(&As[0][0]);
    const uint32_t bs_base0 = (uint32_t)__cvta_generic_to_shared(&Bs[0][0]);
    const uint32_t buf_bytes = 128 * 16 * 4;

    int lr[4];
#pragma unroll
    for (int i = 0; i < 4; ++i) lr[i] = (tid + 128 * i) >> 2;
    const int lc = tid & 3;

    uint32_t sdst[4];
#pragma unroll
    for (int i = 0; i < 4; ++i) sdst[i] = sw16(lr[i], lc) * 16;

    float acc[4][8][4];
#pragma unroll
    for (int mt = 0; mt < 4; ++mt)
#pragma unroll
        for (int nt = 0; nt < 8; ++nt)
#pragma unroll
            for (int i = 0; i < 4; ++i) acc[mt][nt][i] = 0.0f;

    auto issue_tile = [&](int st, int k0) {
        const uint32_t as_s = as_base0 + (uint32_t)st * buf_bytes;
        const uint32_t bs_s = bs_base0 + (uint32_t)st * buf_bytes;
#pragma unroll
        for (int i = 0; i < 4; ++i)
            cp_async16(as_s + sdst[i], &A[(size_t)(bm + lr[i]) * lda + k0 + lc * 4]);
#pragma unroll
        for (int i = 0; i < 4; ++i)
            cp_async16(bs_s + sdst[i], &B[(size_t)(bn + lr[i]) * ldb + k0 + lc * 4]);
    };

    auto compute_tile = [&](int st) {
        const uint32_t as_b = as_base0 + (uint32_t)st * buf_bytes;
        const uint32_t bs_b = bs_base0 + (uint32_t)st * buf_bytes;
#pragma unroll
        for (int kk = 0; kk < 2; ++kk) {
            uint32_t af[4][4];
#pragma unroll
            for (int mt = 0; mt < 4; ++mt) {
                int m = m_base + mt * 16 + a_row;
                int c = 2 * kk + a_csel;
                ldsm4(af[mt], as_b + sw16(m, c) * 16);
            }
            uint32_t bf[4][4];
#pragma unroll
            for (int np = 0; np < 4; ++np) {
                int n = n_base + np * 16 + b_row;
                int c = 2 * kk + b_csel;
                ldsm4(bf[np], bs_b + sw16(n, c) * 16);
            }
#pragma unroll
            for (int mt = 0; mt < 4; ++mt)
#pragma unroll
                for (int nt = 0; nt < 8; ++nt)
                    mma_tf32(acc[mt][nt], af[mt],
                             bf[nt >> 1][(nt & 1) * 2],
                             bf[nt >> 1][(nt & 1) * 2 + 1]);
        }
    };

    const int niter = kCount / 16;

    issue_tile(0, kBegin);
    CP_COMMIT();
    if (niter > 1) issue_tile(1, kBegin + 16);
    CP_COMMIT();

    for (int it = 0; it < niter; ++it) {
        CP_WAIT1();
        __syncthreads();
        const int nx = it + 2;
        if (nx < niter) issue_tile(nx - (nx / 3) * 3, kBegin + nx * 16);
        CP_COMMIT();
        compute_tile(it - (it / 3) * 3);
    }

    // --- writeback ---
    const int g = lane >> 2;
    const int tq = lane & 3;
#pragma unroll
    for (int mt = 0; mt < 4; ++mt) {
        const int r0 = bm + m_base + mt * 16 + g;
        const int r1 = r0 + 8;
#pragma unroll
        for (int nt = 0; nt < 8; ++nt) {
            const int col = bn + n_base + nt * 8 + tq * 2;
            float2 v0, v1;
            if (MODE == 1) {
                v0.x = rnd_tf32(__expf(alpha * acc[mt][nt][0]));
                v0.y = rnd_tf32(__expf(alpha * acc[mt][nt][1]));
                v1.x = rnd_tf32(__expf(alpha * acc[mt][nt][2]));
                v1.y = rnd_tf32(__expf(alpha * acc[mt][nt][3]));
            } else {
                v0.x = acc[mt][nt][0]; v0.y = acc[mt][nt][1];
                v1.x = acc[mt][nt][2]; v1.y = acc[mt][nt][3];
            }
            *reinterpret_cast<float2*>(&C[(size_t)r0 * ldc + col]) = v0;
            *reinterpret_cast<float2*>(&C[(size_t)r1 * ldc + col]) = v1;
        }
    }
}

// ---------------------------------------------------------------------------
// Pipelined batched QKV projection: grid (6, 32, 3); z selects Wt / output.
// Same mainloop as gemm_pipe, but A (= x, raw fp32) fragments get cvt;
// B (= Wt, pre-rounded tf32) fragments don't.
// z=0 -> Q[r][c], z=1 -> K[r][c], z=2 -> Vt[c][r] (transposed write).
// ---------------------------------------------------------------------------
__global__ void __launch_bounds__(128, 2)
proj_pipe(const float* __restrict__ A, const float* __restrict__ Wt,
          float* __restrict__ Qo, float* __restrict__ Ko, float* __restrict__ Vt)
{
    __shared__ float As[3][128 * 16];
    __shared__ float Bs[3][128 * 16];

    const int tid  = threadIdx.x;
    const int lane = tid & 31;
    const int wid  = tid >> 5;
    const int bm = blockIdx.y * 128;
    const int bn = blockIdx.x * 128;
    const int z  = blockIdx.z;
    const float* B = Wt + (size_t)z * DIN * DOUT;

    const int lda = DIN, ldb = DIN;

    const int warp_m = wid & 1;
    const int warp_n = wid >> 1;
    const int m_base = warp_m * 64;
    const int n_base = warp_n * 64;

    const int a_row  = lane & 15;
    const int a_csel = (lane >> 4) & 1;
    const int b_row  = (lane & 7) + ((lane & 16) >> 1);
    const int b_csel = (lane >> 3) & 1;

    const uint32_t as_base0 = (uint32_t)__cvta_generic_to_shared(&As[0][0]);
    const uint32_t bs_base0 = (uint32_t)__cvta_generic_to_shared(&Bs[0][0]);
    const uint32_t buf_bytes = 128 * 16 * 4;

    int lr[4];
#pragma unroll
    for (int i = 0; i < 4; ++i) lr[i] = (tid + 128 * i) >> 2;
    const int lc = tid & 3;

    uint32_t sdst[4];
#pragma unroll
    for (int i = 0; i < 4; ++i) sdst[i] = sw16(lr[i], lc) * 16;

    float acc[4][8][4];
#pragma unroll
    for (int mt = 0; mt < 4; ++mt)
#pragma unroll
        for (int nt = 0; nt < 8; ++nt)
#pragma unroll
            for (int i = 0; i < 4; ++i) acc[mt][nt][i] = 0.0f;

    auto issue_tile = [&](int st, int k0) {
        const uint32_t as_s = as_base0 + (uint32_t)st * buf_bytes;
        const uint32_t bs_s = bs_base0 + (uint32_t)st * buf_bytes;
#pragma unroll
        for (int i = 0; i < 4; ++i)
            cp_async16(as_s + sdst[i], &A[(size_t)(bm + lr[i]) * lda + k0 + lc * 4]);
#pragma unroll
        for (int i = 0; i < 4; ++i)
            cp_async16(bs_s + sdst[i], &B[(size_t)(bn + lr[i]) * ldb + k0 + lc * 4]);
    };

    auto compute_tile = [&](int st) {
        const uint32_t as_b = as_base0 + (uint32_t)st * buf_bytes;
        const uint32_t bs_b = bs_base0 + (uint32_t)st * buf_bytes;
#pragma unroll
        for (int kk = 0; kk < 2; ++kk) {
            uint32_t af[4][4];
#pragma unroll
            for (int mt = 0; mt < 4; ++mt) {
                int m = m_base + mt * 16 + a_row;
                int c = 2 * kk + a_csel;
                ldsm4(af[mt], as_b + sw16(m, c) * 16);
#pragma unroll
                for (int i = 0; i < 4; ++i) af[mt][i] = bits2tf32(af[mt][i]);
            }
            uint32_t bf[4][4];
#pragma unroll
            for (int np = 0; np < 4; ++np) {
                int n = n_base + np * 16 + b_row;
                int c = 2 * kk + b_csel;
                ldsm4(bf[np], bs_b + sw16(n, c) * 16);
            }
#pragma unroll
            for (int mt = 0; mt < 4; ++mt)
#pragma unroll
                for (int nt = 0; nt < 8; ++nt)
                    mma_tf32(acc[mt][nt], af[mt],
                             bf[nt >> 1][(nt & 1) * 2],
                             bf[nt >> 1][(nt & 1) * 2 + 1]);
        }
    };

    const int niter = DIN / 16;   // 48

    issue_tile(0, 0);
    CP_COMMIT();
    issue_tile(1, 16);
    CP_COMMIT();

    for (int it = 0; it < niter; ++it) {
        CP_WAIT1();
        __syncthreads();
        const int nx = it + 2;
        if (nx < niter) issue_tile(nx - (nx / 3) * 3, nx * 16);
        CP_COMMIT();
        compute_tile(it - (it / 3) * 3);
    }

    // --- writeback (tf32-rounded) ---
    const int g = lane >> 2;
    const int tq = lane & 3;
    if (z < 2) {
        float* C = (z == 0) ? Qo : Ko;
#pragma unroll
        for (int mt = 0; mt < 4; ++mt) {
            const int r0 = bm + m_base + mt * 16 + g;
            const int r1 = r0 + 8;
#pragma unroll
            for (int nt = 0; nt < 8; ++nt) {
                const int col = bn + n_base + nt * 8 + tq * 2;
                float2 v0, v1;
                v0.x = rnd_tf32(acc[mt][nt][0]); v0.y = rnd_tf32(acc[mt][nt][1]);
                v1.x = rnd_tf32(acc[mt][nt][2]); v1.y = rnd_tf32(acc[mt][nt][3]);
                *reinterpret_cast<float2*>(&C[(size_t)r0 * DOUT + col]) = v0;
                *reinterpret_cast<float2*>(&C[(size_t)r1 * DOUT + col]) = v1;
            }
        }
    } else {
        // Vt[col][row] = value  (transposed write; lanes sharing tq give
        // 8 consecutive rows -> 32B sectors)
#pragma unroll
        for (int mt = 0; mt < 4; ++mt) {
            const int r0 = bm + m_base + mt * 16 + g;
            const int r1 = r0 + 8;
#pragma unroll
            for (int nt = 0; nt < 8; ++nt) {
                const int col = bn + n_base + nt * 8 + tq * 2;
                Vt[(size_t)(col + 0) * SEQ + r0] = rnd_tf32(acc[mt][nt][0]);
                Vt[(size_t)(col + 1) * SEQ + r0] = rnd_tf32(acc[mt][nt][1]);
                Vt[(size_t)(col + 0) * SEQ + r1] = rnd_tf32(acc[mt][nt][2]);
                Vt[(size_t)(col + 1) * SEQ + r1] = rnd_tf32(acc[mt][nt][3]);
            }
        }
    }
}

// ---------------------------------------------------------------------------
// Weight transpose + tf32 round: Wt[z][n][k] = tf32(W[z][k][n]).
// ---------------------------------------------------------------------------
__global__ void __launch_bounds__(256)
transpose_w(const float* __restrict__ Wq, const float* __restrict__ Wk,
            const float* __restrict__ Wv, float* __restrict__ Wt)
{
    __shared__ float ts[32][33];
    const int tx = threadIdx.x;        // 0..31
    const int ty = threadIdx.y;        // 0..7
    const int n0 = blockIdx.x * 32;
    const int k0 = blockIdx.y * 32;
    const int z  = blockIdx.z;
    const float* W = (z == 0) ? Wq : (z == 1) ? Wk : Wv;
    float* Wo = Wt + (size_t)z * DIN * DOUT;

#pragma unroll
    for (int j = 0; j < 4; ++j) {
        int k = k0 + ty + j * 8;
        ts[ty + j * 8][tx] = W[(size_t)k * DOUT + n0 + tx];
    }
    __syncthreads();
#pragma unroll
    for (int j = 0; j < 4; ++j) {
        int n = n0 + ty + j * 8;
        Wo[(size_t)n * DIN + k0 + tx] = rnd_tf32(ts[tx][ty + j * 8]);
    }
}

// ---------------------------------------------------------------------------
// Reduce partials + apply row normalization.
// ---------------------------------------------------------------------------
__global__ void __launch_bounds__(256)
reduce_av(const float* __restrict__ P, const float* __restrict__ inv,
          float* __restrict__ out)
{
    const size_t stride = (size_t)SEQ * DOUT;
    const size_t i4 = (size_t)blockIdx.x * 256 + threadIdx.x;
    const size_t base = i4 * 4;
    const int row = (int)(base / DOUT);
    const float s = inv[row];

    float4 a = *reinterpret_cast<const float4*>(&P[base]);
    float4 b = *reinterpret_cast<const float4*>(&P[stride + base]);
    float4 c = *reinterpret_cast<const float4*>(&P[2 * stride + base]);
    float4 o;
    o.x = (a.x + b.x + c.x) * s;
    o.y = (a.y + b.y + c.y) * s;
    o.z = (a.z + b.z + c.z) * s;
    o.w = (a.w + b.w + c.w) * s;
    *reinterpret_cast<float4*>(&out[base]) = o;
}

// ---------------------------------------------------------------------------
// Row-sum reciprocal: inv[row] = 1 / sum(E[row, :]). Deterministic.
// ---------------------------------------------------------------------------
__global__ void __launch_bounds__(256)
rowinv_kernel(const float* __restrict__ E, float* __restrict__ inv)
{
    const int row = blockIdx.x;
    const int tid = threadIdx.x;
    const float* p = E + (size_t)row * SEQ;

    __shared__ float sm_red[8];

    float s = 0.0f;
#pragma unroll
    for (int it = 0; it < 4; ++it) {
        float4 t = *reinterpret_cast<const float4*>(&p[it * 1024 + tid * 4]);
        s += t.x + t.y + t.z + t.w;
    }
#pragma unroll
    for (int o = 16; o > 0; o >>= 1) s += __shfl_xor_sync(0xffffffffu, s, o);
    if ((tid & 31) == 0) sm_red[tid >> 5] = s;
    __syncthreads();
    if (tid == 0) {
        float ss = sm_red[0];
#pragma unroll
        for (int w = 1; w < 8; ++w) ss += sm_red[w];
        inv[row] = 1.0f / ss;
    }
}

// ---------------------------------------------------------------------------
extern "C" void kernel_launch(void* const* d_in, const int* in_sizes, int n_in,
                              void* d_out, int out_size)
{
    const float* x  = (const float*)d_in[0];
    const float* Wq = (const float*)d_in[1];
    const float* Wk = (const float*)d_in[2];
    const float* Wv = (const float*)d_in[3];
    float* out = (float*)d_out;

    float* Wt;  cudaGetSymbolAddress((void**)&Wt,  g_Wt);
    float* Q;   cudaGetSymbolAddress((void**)&Q,   g_Q);
    float* K_;  cudaGetSymbolAddress((void**)&K_,  g_K);
    float* Vt;  cudaGetSymbolAddress((void**)&Vt,  g_Vt);
    float* E;   cudaGetSymbolAddress((void**)&E,   g_E);
    float* inv; cudaGetSymbolAddress((void**)&inv, g_inv);
    float* P;   cudaGetSymbolAddress((void**)&P,   g_P);

    const float inv_sqrt_d = 0.036084391824351615f;  // 1/sqrt(768)

    dim3 grid_wt(DOUT / 32, DIN / 32, 3);     // (24, 24, 3)
    dim3 blk_tr(32, 8);
    dim3 grid_proj(DOUT / 128, SEQ / 128, 3); // (6, 32, 3) batched QKV
    dim3 grid_ss(SEQ / 128, SEQ / 128);       // (32, 32)
    dim3 grid_av(DOUT / 128, SEQ / 128, 3);   // (6, 32, 3) split-K

    // Wt[z] = tf32(W[z]^T)
    transpose_w<<<grid_wt, blk_tr>>>(Wq, Wk, Wv, Wt);

    // Q, K (row-major) and Vt (transposed) in one pipelined launch (576 CTAs)
    proj_pipe<<<grid_proj, 128>>>(x, Wt, Q, K_, Vt);

    // E = tf32(exp(Q @ K^T / sqrt(d)))   (cvt-free mainloop)
    gemm_pipe<1><<<grid_ss, 128>>>(Q, K_, E, DIN, DIN, SEQ, DIN, inv_sqrt_d);

    // inv[row] = 1 / rowsum(E)
    rowinv_kernel<<<SEQ, 256>>>(E, inv);

    // P[z] = E[:, Kz] @ Vt[:, Kz]^T   (split-K=3 in ONE 576-CTA launch)
    gemm_pipe<3><<<grid_av, 128>>>(E, Vt, P, SEQ, SEQ, DOUT, SEQ, 1.0f);

    // out = (P0 + P1 + P2) * inv[row]
    reduce_av<<<(SEQ * DOUT) / (256 * 4), 256>>>(P, inv, out);
}

// round 16
// speedup vs baseline: 2.5065x; 1.8327x over previous
#include <cuda_runtime.h>
#include <cuda_fp16.h>
#include <cstdint>

#define SEQ  4096
#define DIN  768
#define DOUT 768

// Scratch (allocation-free: __device__ globals).
__device__ __half g_xh[SEQ * DIN];          // x converted to fp16
__device__ __half g_Wt[3][DIN * DOUT];      // W^T, fp16
__device__ __half g_Q[SEQ * DOUT];
__device__ __half g_K[SEQ * DOUT];
__device__ __half g_Vt[DOUT * SEQ];         // V^T, fp16
__device__ __half g_E[(size_t)SEQ * SEQ];   // exp(scores), fp16 (33 MB)
__device__ float  g_inv[SEQ];               // 1 / rowsum(E)
__device__ float  g_P[3][SEQ * DOUT];       // AV split-K partials (fp32)

// Split-K partition of K=4096 into 3 chunks (multiples of 32 for BK=32).
#define AV_K0 1376
#define AV_K1 1344   // middle; z=2 chunk is 1376 again

// ---------------------------------------------------------------------------
// helpers
// ---------------------------------------------------------------------------
__device__ __forceinline__ void ldsm4(uint32_t r[4], uint32_t saddr) {
    asm volatile("ldmatrix.sync.aligned.m8n8.x4.shared.b16 {%0,%1,%2,%3}, [%4];"
                 : "=r"(r[0]), "=r"(r[1]), "=r"(r[2]), "=r"(r[3])
                 : "r"(saddr));
}

// fp16 mma: D(f32) += A(f16,4reg) * B(f16,2reg), m16n8k16
__device__ __forceinline__ void mma_f16(float c[4],
                                        const uint32_t a[4],
                                        uint32_t b0, uint32_t b1) {
    asm volatile(
        "mma.sync.aligned.m16n8k16.row.col.f32.f16.f16.f32 "
        "{%0,%1,%2,%3}, {%4,%5,%6,%7}, {%8,%9}, {%0,%1,%2,%3};"
        : "+f"(c[0]), "+f"(c[1]), "+f"(c[2]), "+f"(c[3])
        : "r"(a[0]), "r"(a[1]), "r"(a[2]), "r"(a[3]), "r"(b0), "r"(b1));
}

__device__ __forceinline__ void cp_async16(uint32_t smem_dst, const void* gmem_src) {
    asm volatile("cp.async.cg.shared.global [%0], [%1], 16;"
                 :: "r"(smem_dst), "l"(gmem_src));
}
#define CP_COMMIT()  asm volatile("cp.async.commit_group;" ::: "memory")
#define CP_WAIT1()   asm volatile("cp.async.wait_group 1;" ::: "memory")

// smem tile: [128 rows][32 halves] = 4 x 16B chunks per row, XOR swizzled
// (identical formula to the validated tf32 path; chunk = 16 bytes).
__device__ __forceinline__ int sw16(int row, int c) {
    return row * 4 + (c ^ ((row >> 1) & 3));
}

// ---------------------------------------------------------------------------
// fp16 pipelined GEMM core: block 128x128, BK=32, 128 threads (4 warps 2x2,
// warp tile 64x64). Both operands half, K-major. 3-stage cp.async ring.
// MODE 1: E = half(exp(alpha * A@B^T)), K=[0,kTot)       (QK^T + exp)
// MODE 3: P[z] = A@B^T over Kz (fp32 out), split-K via blockIdx.z
// ---------------------------------------------------------------------------
template <int MODE>
__global__ void __launch_bounds__(128, 2)
hgemm_pipe(const __half* __restrict__ A, const __half* __restrict__ B,
           __half* __restrict__ Ch, float* __restrict__ Cf,
           int lda, int ldb, int ldc, int kTot, float alpha)
{
    __shared__ __align__(16) __half As[3][128 * 32];   // 8 KB / stage
    __shared__ __align__(16) __half Bs[3][128 * 32];

    const int tid  = threadIdx.x;
    const int lane = tid & 31;
    const int wid  = tid >> 5;
    const int bm = blockIdx.y * 128;
    const int bn = blockIdx.x * 128;

    int kBegin, kCount;
    float* CF = Cf;
    if (MODE == 3) {
        const int z = blockIdx.z;
        kBegin = (z == 0) ? 0 : ((z == 1) ? AV_K0 : (AV_K0 + AV_K1));
        kCount = (z == 1) ? AV_K1 : AV_K0;
        CF = Cf + (size_t)z * SEQ * DOUT;
    } else {
        kBegin = 0; kCount = kTot;
    }

    const int warp_m = wid & 1;
    const int warp_n = wid >> 1;
    const int m_base = warp_m * 64;
    const int n_base = warp_n * 64;

    // fp16 m16n8k16 ldmatrix lane mapping (derived; mirrors validated math)
    const int a_row  = lane & 15;                        // rows 0..15
    const int a_csel = lane >> 4;                        // k-half 0/1
    const int b_row  = (lane & 7) + ((lane & 16) >> 1);  // n row within 16
    const int b_csel = (lane >> 3) & 1;                  // k-half 0/1

    const uint32_t as_base0 = (uint32_t)__cvta_generic_to_shared(&As[0][0]);
    const uint32_t bs_base0 = (uint32_t)__cvta_generic_to_shared(&Bs[0][0]);
    const uint32_t buf_bytes = 128 * 32 * 2;             // 8192

    // loader: tile = 128 rows x 4 chunks(16B) = 512; 128 threads x 4 each
    int lr[4];
#pragma unroll
    for (int i = 0; i < 4; ++i) lr[i] = (tid + 128 * i) >> 2;
    const int lc = tid & 3;
    uint32_t sdst[4];
#pragma unroll
    for (int i = 0; i < 4; ++i) sdst[i] = sw16(lr[i], lc) * 16;

    float acc[4][8][4];
#pragma unroll
    for (int mt = 0; mt < 4; ++mt)
#pragma unroll
        for (int nt = 0; nt < 8; ++nt)
#pragma unroll
            for (int i = 0; i < 4; ++i) acc[mt][nt][i] = 0.0f;

    auto issue_tile = [&](int st, int k0) {
        const uint32_t as_s = as_base0 + (uint32_t)st * buf_bytes;
        const uint32_t bs_s = bs_base0 + (uint32_t)st * buf_bytes;
#pragma unroll
        for (int i = 0; i < 4; ++i)
            cp_async16(as_s + sdst[i], &A[(size_t)(bm + lr[i]) * lda + k0 + lc * 8]);
#pragma unroll
        for (int i = 0; i < 4; ++i)
            cp_async16(bs_s + sdst[i], &B[(size_t)(bn + lr[i]) * ldb + k0 + lc * 8]);
    };

    auto compute_tile = [&](int st) {
        const uint32_t as_b = as_base0 + (uint32_t)st * buf_bytes;
        const uint32_t bs_b = bs_base0 + (uint32_t)st * buf_bytes;
#pragma unroll
        for (int kh = 0; kh < 2; ++kh) {       // two k16 steps per BK=32
            uint32_t af[4][4];
#pragma unroll
            for (int mt = 0; mt < 4; ++mt) {
                int m = m_base + mt * 16 + a_row;
                int c = kh * 2 + a_csel;
                ldsm4(af[mt], as_b + sw16(m, c) * 16);
            }
            uint32_t bf[4][4];
#pragma unroll
            for (int np = 0; np < 4; ++np) {
                int n = n_base + np * 16 + b_row;
                int c = kh * 2 + b_csel;
                ldsm4(bf[np], bs_b + sw16(n, c) * 16);
            }
#pragma unroll
            for (int mt = 0; mt < 4; ++mt)
#pragma unroll
                for (int nt = 0; nt < 8; ++nt)
                    mma_f16(acc[mt][nt], af[mt],
                            bf[nt >> 1][(nt & 1) * 2],
                            bf[nt >> 1][(nt & 1) * 2 + 1]);
        }
    };

    const int niter = kCount / 32;

    issue_tile(0, kBegin);
    CP_COMMIT();
    if (niter > 1) issue_tile(1, kBegin + 32);
    CP_COMMIT();

    for (int it = 0; it < niter; ++it) {
        CP_WAIT1();
        __syncthreads();
        const int nx = it + 2;
        if (nx < niter) issue_tile(nx - (nx / 3) * 3, kBegin + nx * 32);
        CP_COMMIT();
        compute_tile(it - (it / 3) * 3);
    }

    // --- writeback (C fragment layout identical to tf32 path) ---
    const int g = lane >> 2;
    const int tq = lane & 3;
#pragma unroll
    for (int mt = 0; mt < 4; ++mt) {
        const int r0 = bm + m_base + mt * 16 + g;
        const int r1 = r0 + 8;
#pragma unroll
        for (int nt = 0; nt < 8; ++nt) {
            const int col = bn + n_base + nt * 8 + tq * 2;
            if (MODE == 1) {
                __half2 h0 = __floats2half2_rn(__expf(alpha * acc[mt][nt][0]),
                                               __expf(alpha * acc[mt][nt][1]));
                __half2 h1 = __floats2half2_rn(__expf(alpha * acc[mt][nt][2]),
                                               __expf(alpha * acc[mt][nt][3]));
                *reinterpret_cast<__half2*>(&Ch[(size_t)r0 * ldc + col]) = h0;
                *reinterpret_cast<__half2*>(&Ch[(size_t)r1 * ldc + col]) = h1;
            } else {
                float2 v0, v1;
                v0.x = acc[mt][nt][0]; v0.y = acc[mt][nt][1];
                v1.x = acc[mt][nt][2]; v1.y = acc[mt][nt][3];
                *reinterpret_cast<float2*>(&CF[(size_t)r0 * ldc + col]) = v0;
                *reinterpret_cast<float2*>(&CF[(size_t)r1 * ldc + col]) = v1;
            }
        }
    }
}

// ---------------------------------------------------------------------------
// fp16 batched QKV projection: grid (6, 32, 3); z selects Wt / output.
// Same mainloop; z=0 -> Q, z=1 -> K, z=2 -> Vt (transposed half writes).
// ---------------------------------------------------------------------------
__global__ void __launch_bounds__(128, 2)
hproj_pipe(const __half* __restrict__ A, const __half* __restrict__ Wt,
           __half* __restrict__ Qo, __half* __restrict__ Ko,
           __half* __restrict__ Vt)
{
    __shared__ __align__(16) __half As[3][128 * 32];
    __shared__ __align__(16) __half Bs[3][128 * 32];

    const int tid  = threadIdx.x;
    const int lane = tid & 31;
    const int wid  = tid >> 5;
    const int bm = blockIdx.y * 128;
    const int bn = blockIdx.x * 128;
    const int z  = blockIdx.z;
    const __half* B = Wt + (size_t)z * DIN * DOUT;

    const int lda = DIN, ldb = DIN;

    const int warp_m = wid & 1;
    const int warp_n = wid >> 1;
    const int m_base = warp_m * 64;
    const int n_base = warp_n * 64;

    const int a_row  = lane & 15;
    const int a_csel = lane >> 4;
    const int b_row  = (lane & 7) + ((lane & 16) >> 1);
    const int b_csel = (lane >> 3) & 1;

    const uint32_t as_base0 = (uint32_t)__cvta_generic_to_shared(&As[0][0]);
    const uint32_t bs_base0 = (uint32_t)__cvta_generic_to_shared(&Bs[0][0]);
    const uint32_t buf_bytes = 128 * 32 * 2;

    int lr[4];
#pragma unroll
    for (int i = 0; i < 4; ++i) lr[i] = (tid + 128 * i) >> 2;
    const int lc = tid & 3;
    uint32_t sdst[4];
#pragma unroll
    for (int i = 0; i < 4; ++i) sdst[i] = sw16(lr[i], lc) * 16;

    float acc[4][8][4];
#pragma unroll
    for (int mt = 0; mt < 4; ++mt)
#pragma unroll
        for (int nt = 0; nt < 8; ++nt)
#pragma unroll
            for (int i = 0; i < 4; ++i) acc[mt][nt][i] = 0.0f;

    auto issue_tile = [&](int st, int k0) {
        const uint32_t as_s = as_base0 + (uint32_t)st * buf_bytes;
        const uint32_t bs_s = bs_base0 + (uint32_t)st * buf_bytes;
#pragma unroll
        for (int i = 0; i < 4; ++i)
            cp_async16(as_s + sdst[i], &A[(size_t)(bm + lr[i]) * lda + k0 + lc * 8]);
#pragma unroll
        for (int i = 0; i < 4; ++i)
            cp_async16(bs_s + sdst[i], &B[(size_t)(bn + lr[i]) * ldb + k0 + lc * 8]);
    };

    auto compute_tile = [&](int st) {
        const uint32_t as_b = as_base0 + (uint32_t)st * buf_bytes;
        const uint32_t bs_b = bs_base0 + (uint32_t)st * buf_bytes;
#pragma unroll
        for (int kh = 0; kh < 2; ++kh) {
            uint32_t af[4][4];
#pragma unroll
            for (int mt = 0; mt < 4; ++mt) {
                int m = m_base + mt * 16 + a_row;
                int c = kh * 2 + a_csel;
                ldsm4(af[mt], as_b + sw16(m, c) * 16);
            }
            uint32_t bf[4][4];
#pragma unroll
            for (int np = 0; np < 4; ++np) {
                int n = n_base + np * 16 + b_row;
                int c = kh * 2 + b_csel;
                ldsm4(bf[np], bs_b + sw16(n, c) * 16);
            }
#pragma unroll
            for (int mt = 0; mt < 4; ++mt)
#pragma unroll
                for (int nt = 0; nt < 8; ++nt)
                    mma_f16(acc[mt][nt], af[mt],
                            bf[nt >> 1][(nt & 1) * 2],
                            bf[nt >> 1][(nt & 1) * 2 + 1]);
        }
    };

    const int niter = DIN / 32;   // 24

    issue_tile(0, 0);
    CP_COMMIT();
    issue_tile(1, 32);
    CP_COMMIT();

    for (int it = 0; it < niter; ++it) {
        CP_WAIT1();
        __syncthreads();
        const int nx = it + 2;
        if (nx < niter) issue_tile(nx - (nx / 3) * 3, nx * 32);
        CP_COMMIT();
        compute_tile(it - (it / 3) * 3);
    }

    const int g = lane >> 2;
    const int tq = lane & 3;
    if (z < 2) {
        __half* C = (z == 0) ? Qo : Ko;
#pragma unroll
        for (int mt = 0; mt < 4; ++mt) {
            const int r0 = bm + m_base + mt * 16 + g;
            const int r1 = r0 + 8;
#pragma unroll
            for (int nt = 0; nt < 8; ++nt) {
                const int col = bn + n_base + nt * 8 + tq * 2;
                __half2 h0 = __floats2half2_rn(acc[mt][nt][0], acc[mt][nt][1]);
                __half2 h1 = __floats2half2_rn(acc[mt][nt][2], acc[mt][nt][3]);
                *reinterpret_cast<__half2*>(&C[(size_t)r0 * DOUT + col]) = h0;
                *reinterpret_cast<__half2*>(&C[(size_t)r1 * DOUT + col]) = h1;
            }
        }
    } else {
        // Vt[col][row] transposed scatter (2B writes; 8 lanes share tq -> 16B runs)
#pragma unroll
        for (int mt = 0; mt < 4; ++mt) {
            const int r0 = bm + m_base + mt * 16 + g;
            const int r1 = r0 + 8;
#pragma unroll
            for (int nt = 0; nt < 8; ++nt) {
                const int col = bn + n_base + nt * 8 + tq * 2;
                Vt[(size_t)(col + 0) * SEQ + r0] = __float2half(acc[mt][nt][0]);
                Vt[(size_t)(col + 1) * SEQ + r0] = __float2half(acc[mt][nt][1]);
                Vt[(size_t)(col + 0) * SEQ + r1] = __float2half(acc[mt][nt][2]);
                Vt[(size_t)(col + 1) * SEQ + r1] = __float2half(acc[mt][nt][3]);
            }
        }
    }
}

// ---------------------------------------------------------------------------
// x fp32 -> fp16
// ---------------------------------------------------------------------------
__global__ void __launch_bounds__(256)
convert_x(const float* __restrict__ x, __half* __restrict__ xh)
{
    const size_t i = ((size_t)blockIdx.x * 256 + threadIdx.x) * 8;
    float4 a = *reinterpret_cast<const float4*>(&x[i]);
    float4 b = *reinterpret_cast<const float4*>(&x[i + 4]);
    __half2 h[4];
    h[0] = __floats2half2_rn(a.x, a.y);
    h[1] = __floats2half2_rn(a.z, a.w);
    h[2] = __floats2half2_rn(b.x, b.y);
    h[3] = __floats2half2_rn(b.z, b.w);
    *reinterpret_cast<uint4*>(&xh[i]) = *reinterpret_cast<uint4*>(h);
}

// ---------------------------------------------------------------------------
// Weight transpose + fp16: Wt[z][n][k] = half(W[z][k][n]).
// ---------------------------------------------------------------------------
__global__ void __launch_bounds__(256)
transpose_w(const float* __restrict__ Wq, const float* __restrict__ Wk,
            const float* __restrict__ Wv, __half* __restrict__ Wt)
{
    __shared__ float ts[32][33];
    const int tx = threadIdx.x;
    const int ty = threadIdx.y;
    const int n0 = blockIdx.x * 32;
    const int k0 = blockIdx.y * 32;
    const int z  = blockIdx.z;
    const float* W = (z == 0) ? Wq : (z == 1) ? Wk : Wv;
    __half* Wo = Wt + (size_t)z * DIN * DOUT;

#pragma unroll
    for (int j = 0; j < 4; ++j) {
        int k = k0 + ty + j * 8;
        ts[ty + j * 8][tx] = W[(size_t)k * DOUT + n0 + tx];
    }
    __syncthreads();
#pragma unroll
    for (int j = 0; j < 4; ++j) {
        int n = n0 + ty + j * 8;
        Wo[(size_t)n * DIN + k0 + tx] = __float2half(ts[tx][ty + j * 8]);
    }
}

// ---------------------------------------------------------------------------
// Row-sum reciprocal over half E. Deterministic.
// ---------------------------------------------------------------------------
__global__ void __launch_bounds__(256)
rowinv_kernel(const __half* __restrict__ E, float* __restrict__ inv)
{
    const int row = blockIdx.x;
    const int tid = threadIdx.x;
    const __half2* p2 = reinterpret_cast<const __half2*>(E + (size_t)row * SEQ);

    __shared__ float sm_red[8];

    float s = 0.0f;
#pragma unroll
    for (int it = 0; it < 8; ++it) {
        float2 f = __half22float2(p2[it * 256 + tid]);
        s += f.x + f.y;
    }
#pragma unroll
    for (int o = 16; o > 0; o >>= 1) s += __shfl_xor_sync(0xffffffffu, s, o);
    if ((tid & 31) == 0) sm_red[tid >> 5] = s;
    __syncthreads();
    if (tid == 0) {
        float ss = sm_red[0];
#pragma unroll
        for (int w = 1; w < 8; ++w) ss += sm_red[w];
        inv[row] = 1.0f / ss;
    }
}

// ---------------------------------------------------------------------------
// Reduce partials + apply row normalization.
// ---------------------------------------------------------------------------
__global__ void __launch_bounds__(256)
reduce_av(const float* __restrict__ P, const float* __restrict__ inv,
          float* __restrict__ out)
{
    const size_t stride = (size_t)SEQ * DOUT;
    const size_t i4 = (size_t)blockIdx.x * 256 + threadIdx.x;
    const size_t base = i4 * 4;
    const int row = (int)(base / DOUT);
    const float s = inv[row];

    float4 a = *reinterpret_cast<const float4*>(&P[base]);
    float4 b = *reinterpret_cast<const float4*>(&P[stride + base]);
    float4 c = *reinterpret_cast<const float4*>(&P[2 * stride + base]);
    float4 o;
    o.x = (a.x + b.x + c.x) * s;
    o.y = (a.y + b.y + c.y) * s;
    o.z = (a.z + b.z + c.z) * s;
    o.w = (a.w + b.w + c.w) * s;
    *reinterpret_cast<float4*>(&out[base]) = o;
}

// ---------------------------------------------------------------------------
extern "C" void kernel_launch(void* const* d_in, const int* in_sizes, int n_in,
                              void* d_out, int out_size)
{
    const float* x  = (const float*)d_in[0];
    const float* Wq = (const float*)d_in[1];
    const float* Wk = (const float*)d_in[2];
    const float* Wv = (const float*)d_in[3];
    float* out = (float*)d_out;

    __half* xh;  cudaGetSymbolAddress((void**)&xh,  g_xh);
    __half* Wt;  cudaGetSymbolAddress((void**)&Wt,  g_Wt);
    __half* Q;   cudaGetSymbolAddress((void**)&Q,   g_Q);
    __half* K_;  cudaGetSymbolAddress((void**)&K_,  g_K);
    __half* Vt;  cudaGetSymbolAddress((void**)&Vt,  g_Vt);
    __half* E;   cudaGetSymbolAddress((void**)&E,   g_E);
    float* inv;  cudaGetSymbolAddress((void**)&inv, g_inv);
    float* P;    cudaGetSymbolAddress((void**)&P,   g_P);

    const float inv_sqrt_d = 0.036084391824351615f;  // 1/sqrt(768)

    dim3 grid_cx((SEQ * DIN) / (256 * 8));    // 1536
    dim3 grid_wt(DOUT / 32, DIN / 32, 3);     // (24, 24, 3)
    dim3 blk_tr(32, 8);
    dim3 grid_proj(DOUT / 128, SEQ / 128, 3); // (6, 32, 3)
    dim3 grid_ss(SEQ / 128, SEQ / 128);       // (32, 32)
    dim3 grid_av(DOUT / 128, SEQ / 128, 3);   // (6, 32, 3)

    // x -> fp16; Wt[z] = half(W[z]^T)
    convert_x<<<grid_cx, 256>>>(x, xh);
    transpose_w<<<grid_wt, blk_tr>>>(Wq, Wk, Wv, Wt);

    // Q, K, Vt in one fp16 pipelined launch (576 CTAs)
    hproj_pipe<<<grid_proj, 128>>>(xh, Wt, Q, K_, Vt);

    // E = half(exp(Q @ K^T / sqrt(d)))
    hgemm_pipe<1><<<grid_ss, 128>>>(Q, K_, E, nullptr, DIN, DIN, SEQ, DIN, inv_sqrt_d);

    // inv[row] = 1 / rowsum(E)
    rowinv_kernel<<<SEQ, 256>>>(E, inv);

    // P[z] = E[:, Kz] @ Vt[:, Kz]^T   (split-K=3 in one launch, fp32 out)
    hgemm_pipe<3><<<grid_av, 128>>>(E, Vt, nullptr, P, SEQ, SEQ, DOUT, SEQ, 1.0f);

    // out = (P0 + P1 + P2) * inv[row]
    reduce_av<<<(SEQ * DOUT) / (256 * 4), 256>>>(P, inv, out);
}